// round 3
// baseline (speedup 1.0000x reference)
#include <cuda_runtime.h>
#include <math.h>

#define NB 32
#define XD 521
#define TD 49
#define CW 64
#define NMODE 256
#define VROW 3136                 // TD*CW
#define V_ELEMS  52283392ull      // NB*XD*VROW
#define A_ELEMS  17072128ull      // NB*XD*16*CW
#define S_ELEMS  524288ull        // NB*NMODE*CW
#define VP_ELEMS 4194304ull       // 8*S_ELEMS
#define WT_ELEMS 4194304ull       // 4*NMODE*CW*CW

__device__ float g_v[V_ELEMS];
__device__ float g_hr[A_ELEMS];
__device__ float g_hi[A_ELEMS];
__device__ float g_vpr[VP_ELEMS];
__device__ float g_vpi[VP_ELEMS];
__device__ float g_sr[S_ELEMS];
__device__ float g_si[S_ELEMS];
__device__ float g_wtr[WT_ELEMS];
__device__ float g_wti[WT_ELEMS];
__device__ float g_etr[16 * 49], g_eti[16 * 49];
__device__ float g_exr[16 * 521], g_exi[16 * 521];
__device__ float g_ctc[16 * 52], g_cts[16 * 52];

__device__ __forceinline__ float gelu_f(float v) {
    return 0.5f * v * (1.0f + erff(v * 0.70710678118654752f));
}

// ---------- twiddle tables ----------
__global__ void k_tables() {
    int idx = blockIdx.x * blockDim.x + threadIdx.x;
    const double PI2 = 6.283185307179586476925287;
    if (idx < 16 * 49) {
        int kt = idx / 49, t = idx % 49;
        double a = -PI2 * (double)((kt * t) % 49) / 49.0;
        g_etr[idx] = (float)cos(a);
        g_eti[idx] = (float)sin(a);
    }
    if (idx < 16 * 521) {
        int kx = idx / 521, xx = idx % 521;
        double a = -PI2 * (double)((kx * xx) % 521) / 521.0;
        g_exr[idx] = (float)cos(a);
        g_exi[idx] = (float)sin(a);
    }
    if (idx < 16 * 52) {
        int kt = idx / 52, t = idx % 52;
        if (t < 49) {
            double a = PI2 * (double)((kt * t) % 49) / 49.0;
            float sc = (float)(1.0 / (521.0 * 49.0)) * (kt == 0 ? 1.0f : 2.0f);
            g_ctc[idx] = sc * (float)cos(a);
            g_cts[idx] = sc * (float)sin(a);
        } else { g_ctc[idx] = 0.f; g_cts[idx] = 0.f; }
    }
}

// ---------- spectral weight transpose: [l][i][o][m] -> [l][m][i][o] ----------
__global__ void k_wt(const float* __restrict__ wr, const float* __restrict__ wi) {
    __shared__ float sh[64 * 65];
    int mc = blockIdx.x, i = blockIdx.y, l = blockIdx.z, tid = threadIdx.x;
    size_t srcbase = ((size_t)(l * 64 + i)) * 64 * 256 + (size_t)mc * 64;
    for (int idx = tid; idx < 4096; idx += 256) {
        int o = idx >> 6, mm = idx & 63;
        sh[o * 65 + mm] = wr[srcbase + (size_t)o * 256 + mm];
    }
    __syncthreads();
    for (int idx = tid; idx < 4096; idx += 256) {
        int mm = idx >> 6, o = idx & 63;
        g_wtr[(((size_t)(l * 256 + mc * 64 + mm)) * 64 + i) * 64 + o] = sh[o * 65 + mm];
    }
    __syncthreads();
    for (int idx = tid; idx < 4096; idx += 256) {
        int o = idx >> 6, mm = idx & 63;
        sh[o * 65 + mm] = wi[srcbase + (size_t)o * 256 + mm];
    }
    __syncthreads();
    for (int idx = tid; idx < 4096; idx += 256) {
        int mm = idx >> 6, o = idx & 63;
        g_wti[(((size_t)(l * 256 + mc * 64 + mm)) * 64 + i) * 64 + o] = sh[o * 65 + mm];
    }
}

// ---------- embed: concat + fc0 into padded v ----------
__global__ void k_embed(const float* __restrict__ u, const float* __restrict__ xin,
                        const float* __restrict__ tin, const float* __restrict__ par,
                        const float* __restrict__ w0, const float* __restrict__ b0) {
    __shared__ float w_sh[14 * 64];
    __shared__ float b_sh[64];
    __shared__ float feat[13];
    __shared__ float tv[40];
    int x = blockIdx.x, b = blockIdx.y, tid = threadIdx.x;
    for (int i = tid; i < 896; i += 256) w_sh[i] = w0[i];
    if (tid < 64) b_sh[tid] = b0[tid];
    if (x < 512) {
        if (tid < 10) feat[tid] = u[((size_t)(b * 512 + x)) * 10 + tid];
        else if (tid < 12) feat[tid] = par[b * 2 + tid - 10];
        else if (tid == 12) feat[tid] = xin[b * 512 + x];
        if (tid >= 32 && tid < 72) tv[tid - 32] = tin[b * 40 + tid - 32];
    }
    __syncthreads();
    int c = tid & 63, tg = tid >> 6;
    size_t base = ((size_t)(b * XD + x)) * VROW;
    for (int t = tg; t < TD; t += 4) {
        float acc = 0.f;
        if (x < 512 && t < 40) {
            acc = b_sh[c];
#pragma unroll
            for (int k = 0; k < 13; k++) acc += feat[k] * w_sh[k * 64 + c];
            acc += tv[t] * w_sh[13 * 64 + c];
        }
        g_v[base + t * 64 + c] = acc;
    }
}

// ---------- forward DFT over t ----------
__global__ void __launch_bounds__(256) k_dft_t() {
    __shared__ float v_sh[VROW];
    __shared__ float etr[784], eti[784];
    int x = blockIdx.x, b = blockIdx.y, tid = threadIdx.x;
    size_t vb = ((size_t)(b * XD + x)) * VROW;
    float4* vs4 = (float4*)v_sh;
    const float4* gv4 = (const float4*)(g_v + vb);
    for (int i = tid; i < 784; i += 256) {
        vs4[i] = gv4[i];
        etr[i] = g_etr[i];
        eti[i] = g_eti[i];
    }
    __syncthreads();
    int cg = tid & 15, kt = tid >> 4;
    float4 ar = make_float4(0, 0, 0, 0), ai = make_float4(0, 0, 0, 0);
#pragma unroll 7
    for (int t = 0; t < 49; t++) {
        float4 v4 = vs4[t * 16 + cg];
        float er = etr[kt * 49 + t], ei = eti[kt * 49 + t];
        ar.x += v4.x * er; ar.y += v4.y * er; ar.z += v4.z * er; ar.w += v4.w * er;
        ai.x += v4.x * ei; ai.y += v4.y * ei; ai.z += v4.z * ei; ai.w += v4.w * ei;
    }
    size_t ab = (((size_t)(b * XD + x)) * 16 + kt) * 64;
    ((float4*)(g_hr + ab))[cg] = ar;
    ((float4*)(g_hi + ab))[cg] = ai;
}

// ---------- forward DFT over x (8 partial chunks, deterministic) ----------
__global__ void __launch_bounds__(512) k_dft_x() {
    __shared__ float exr[16 * 66], exi[16 * 66];
    int p = blockIdx.x, b = blockIdx.y, tid = threadIdx.x;
    int xs = p * 66;
    int cnt = min(66, XD - xs);
    for (int i = tid; i < 16 * cnt; i += 512) {
        int kx = i / cnt, xl = i % cnt;
        exr[kx * 66 + xl] = g_exr[kx * 521 + xs + xl];
        exi[kx * 66 + xl] = g_exi[kx * 521 + xs + xl];
    }
    __syncthreads();
    int c = tid & 63, kp = tid >> 6;
    int kt0 = kp * 2;
    float vr0[16], vi0[16], vr1[16], vi1[16];
#pragma unroll
    for (int kx = 0; kx < 16; kx++) { vr0[kx] = vi0[kx] = vr1[kx] = vi1[kx] = 0.f; }
    for (int xl = 0; xl < cnt; xl++) {
        size_t base = ((size_t)(b * XD + xs + xl)) * 16;
        float a0r = g_hr[(base + kt0) * 64 + c], a0i = g_hi[(base + kt0) * 64 + c];
        float a1r = g_hr[(base + kt0 + 1) * 64 + c], a1i = g_hi[(base + kt0 + 1) * 64 + c];
#pragma unroll
        for (int kx = 0; kx < 16; kx++) {
            float er = exr[kx * 66 + xl], ei = exi[kx * 66 + xl];
            vr0[kx] += a0r * er - a0i * ei;
            vi0[kx] += a0r * ei + a0i * er;
            vr1[kx] += a1r * er - a1i * ei;
            vi1[kx] += a1r * ei + a1i * er;
        }
    }
    size_t ob = ((size_t)(p * 32 + b)) * NMODE * 64;
#pragma unroll
    for (int kx = 0; kx < 16; kx++) {
        g_vpr[ob + (kx * 16 + kt0) * 64 + c] = vr0[kx];
        g_vpi[ob + (kx * 16 + kt0) * 64 + c] = vi0[kx];
        g_vpr[ob + (kx * 16 + kt0 + 1) * 64 + c] = vr1[kx];
        g_vpi[ob + (kx * 16 + kt0 + 1) * 64 + c] = vi1[kx];
    }
}

// ---------- per-mode complex channel mix ----------
__global__ void __launch_bounds__(256) k_mix(int l) {
    extern __shared__ float sh[];
    float* wr_sh = sh;
    float* wi_sh = sh + 4096;
    float* vrs = sh + 8192;
    float* vis = sh + 10240;
    int m = blockIdx.x, tid = threadIdx.x;
    size_t wb = ((size_t)(l * 256 + m)) * 4096;
    for (int i = tid; i < 4096; i += 256) {
        wr_sh[i] = g_wtr[wb + i];
        wi_sh[i] = g_wti[wb + i];
    }
    for (int i = tid; i < 2048; i += 256) {
        int bb = i >> 6, c = i & 63;
        size_t o = (((size_t)bb) * NMODE + m) * 64 + c;
        float sr = 0.f, si = 0.f;
#pragma unroll
        for (int pp = 0; pp < 8; pp++) {
            sr += g_vpr[(size_t)pp * S_ELEMS + o];
            si += g_vpi[(size_t)pp * S_ELEMS + o];
        }
        vrs[i] = sr;
        vis[i] = si;
    }
    __syncthreads();
    int o = tid & 63, bg = tid >> 6;
    for (int bb = bg; bb < 32; bb += 4) {
        float sr = 0.f, si = 0.f;
#pragma unroll
        for (int c = 0; c < 64; c++) {
            float vr = vrs[bb * 64 + c], vi = vis[bb * 64 + c];
            float wr = wr_sh[c * 64 + o], wi = wi_sh[c * 64 + o];
            sr += vr * wr - vi * wi;
            si += vr * wi + vi * wr;
        }
        size_t ob = (((size_t)bb) * NMODE + m) * 64 + o;
        g_sr[ob] = sr;
        g_si[ob] = si;
    }
}

// ---------- inverse DFT over x ----------
__global__ void __launch_bounds__(256) k_idft_x() {
    __shared__ float ssr[1024], ssi[1024];
    int xc = blockIdx.x, b = blockIdx.y, tid = threadIdx.x;
    int lane = tid & 31, wp = tid >> 5;
    int x = xc * 8 + wp;
    bool valid = (x < XD);
    float hr0[16], hi0[16], hr1[16], hi1[16];
#pragma unroll
    for (int kt = 0; kt < 16; kt++) { hr0[kt] = hi0[kt] = hr1[kt] = hi1[kt] = 0.f; }
    for (int kx = 0; kx < 16; kx++) {
        __syncthreads();
        size_t sb = (((size_t)b) * NMODE + kx * 16) * 64;
        for (int i = tid; i < 1024; i += 256) {
            ssr[i] = g_sr[sb + i];
            ssi[i] = g_si[sb + i];
        }
        __syncthreads();
        if (valid) {
            float er = g_exr[kx * 521 + x], ei = g_exi[kx * 521 + x];
#pragma unroll
            for (int kt = 0; kt < 16; kt++) {
                float s0r = ssr[kt * 64 + lane], s0i = ssi[kt * 64 + lane];
                float s1r = ssr[kt * 64 + lane + 32], s1i = ssi[kt * 64 + lane + 32];
                hr0[kt] += s0r * er + s0i * ei;
                hi0[kt] += s0i * er - s0r * ei;
                hr1[kt] += s1r * er + s1i * ei;
                hi1[kt] += s1i * er - s1r * ei;
            }
        }
    }
    if (valid) {
        size_t hb = ((size_t)(b * XD + x)) * 1024;
#pragma unroll
        for (int kt = 0; kt < 16; kt++) {
            g_hr[hb + kt * 64 + lane] = hr0[kt];
            g_hr[hb + kt * 64 + lane + 32] = hr1[kt];
            g_hi[hb + kt * 64 + lane] = hi0[kt];
            g_hi[hb + kt * 64 + lane + 32] = hi1[kt];
        }
    }
}

// ---------- fused inverse-DFT-t + pointwise conv + bias + gelu, in-place ----------
__global__ void __launch_bounds__(256) k_conv_inv(const float* __restrict__ wconv,
                                                 const float* __restrict__ wbias,
                                                 int l, int dogelu) {
    __shared__ float v_sh[VROW];
    __shared__ float wT[4096];
    __shared__ float hrs[1024], his[1024];
    __shared__ float ctc[832], cts[832];
    __shared__ float bsh[64];
    int x = blockIdx.x, b = blockIdx.y, tid = threadIdx.x;
    size_t vb = ((size_t)(b * XD + x)) * VROW;
    for (int i = tid; i < 784; i += 256) ((float4*)v_sh)[i] = ((const float4*)(g_v + vb))[i];
    for (int i = tid; i < 4096; i += 256) {
        int o = i >> 6, c = i & 63;
        wT[c * 64 + o] = wconv[l * 4096 + i];
    }
    size_t hb = ((size_t)(b * XD + x)) * 1024;
    for (int i = tid; i < 1024; i += 256) {
        hrs[i] = g_hr[hb + i];
        his[i] = g_hi[hb + i];
    }
    for (int i = tid; i < 832; i += 256) {
        ctc[i] = g_ctc[i];
        cts[i] = g_cts[i];
    }
    if (tid < 64) bsh[tid] = wbias[l * 64 + tid];
    __syncthreads();

    int og = tid & 15, tg = tid >> 4;
    int t0 = tg * 4;
    if (t0 < 49) {
        float4 bb4 = ((float4*)bsh)[og];
        float4 a0 = bb4, a1 = bb4, a2 = bb4, a3 = bb4;
#pragma unroll 8
        for (int c = 0; c < 64; c++) {
            float4 w4 = ((float4*)wT)[c * 16 + og];
            float v0 = v_sh[(t0 + 0) * 64 + c];
            float v1 = v_sh[(t0 + 1) * 64 + c];
            float v2 = v_sh[(t0 + 2) * 64 + c];
            float v3 = (t0 + 3 < 49) ? v_sh[(t0 + 3) * 64 + c] : 0.f;
            a0.x += v0 * w4.x; a0.y += v0 * w4.y; a0.z += v0 * w4.z; a0.w += v0 * w4.w;
            a1.x += v1 * w4.x; a1.y += v1 * w4.y; a1.z += v1 * w4.z; a1.w += v1 * w4.w;
            a2.x += v2 * w4.x; a2.y += v2 * w4.y; a2.z += v2 * w4.z; a2.w += v2 * w4.w;
            a3.x += v3 * w4.x; a3.y += v3 * w4.y; a3.z += v3 * w4.z; a3.w += v3 * w4.w;
        }
#pragma unroll
        for (int kt = 0; kt < 16; kt++) {
            float4 hr4 = ((float4*)hrs)[kt * 16 + og];
            float4 hi4 = ((float4*)his)[kt * 16 + og];
            float c0 = ctc[kt * 52 + t0 + 0], s0 = cts[kt * 52 + t0 + 0];
            float c1 = ctc[kt * 52 + t0 + 1], s1 = cts[kt * 52 + t0 + 1];
            float c2 = ctc[kt * 52 + t0 + 2], s2 = cts[kt * 52 + t0 + 2];
            float c3 = ctc[kt * 52 + t0 + 3], s3 = cts[kt * 52 + t0 + 3];
            a0.x += hr4.x * c0 - hi4.x * s0; a0.y += hr4.y * c0 - hi4.y * s0;
            a0.z += hr4.z * c0 - hi4.z * s0; a0.w += hr4.w * c0 - hi4.w * s0;
            a1.x += hr4.x * c1 - hi4.x * s1; a1.y += hr4.y * c1 - hi4.y * s1;
            a1.z += hr4.z * c1 - hi4.z * s1; a1.w += hr4.w * c1 - hi4.w * s1;
            a2.x += hr4.x * c2 - hi4.x * s2; a2.y += hr4.y * c2 - hi4.y * s2;
            a2.z += hr4.z * c2 - hi4.z * s2; a2.w += hr4.w * c2 - hi4.w * s2;
            a3.x += hr4.x * c3 - hi4.x * s3; a3.y += hr4.y * c3 - hi4.y * s3;
            a3.z += hr4.z * c3 - hi4.z * s3; a3.w += hr4.w * c3 - hi4.w * s3;
        }
        float4 accs[4] = {a0, a1, a2, a3};
#pragma unroll
        for (int tt = 0; tt < 4; tt++) {
            int t = t0 + tt;
            if (t < 49) {
                float4 a = accs[tt];
                if (dogelu) {
                    a.x = gelu_f(a.x); a.y = gelu_f(a.y);
                    a.z = gelu_f(a.z); a.w = gelu_f(a.w);
                }
                ((float4*)(g_v + vb))[t * 16 + og] = a;
            }
        }
    }
}

// ---------- crop + fc1 + gelu + fc2 ----------
__global__ void __launch_bounds__(256) k_final(const float* __restrict__ w1,
                                               const float* __restrict__ b1,
                                               const float* __restrict__ w2,
                                               const float* __restrict__ b2,
                                               float* __restrict__ out) {
    __shared__ float w1s[64 * 128];
    __shared__ float vs[40 * 64];
    __shared__ float b1s[128], w2s[128];
    __shared__ float b2s;
    int x = blockIdx.x, b = blockIdx.y, tid = threadIdx.x;
    for (int i = tid; i < 8192; i += 256) w1s[i] = w1[i];
    if (tid < 128) { b1s[tid] = b1[tid]; w2s[tid] = w2[tid]; }
    if (tid == 0) b2s = b2[0];
    size_t vb = ((size_t)(b * XD + x)) * VROW;
    for (int i = tid; i < 640; i += 256) ((float4*)vs)[i] = ((const float4*)(g_v + vb))[i];
    __syncthreads();
    int lane = tid & 31, wp = tid >> 5;
    // each lane handles hidden quad o = lane*4 .. lane*4+3; 5 t-values per warp
    float h[5][4];
#pragma unroll
    for (int s = 0; s < 5; s++) {
        float4 bq = ((float4*)b1s)[lane];
        h[s][0] = bq.x; h[s][1] = bq.y; h[s][2] = bq.z; h[s][3] = bq.w;
    }
#pragma unroll 4
    for (int c = 0; c < 64; c++) {
        float4 w4 = ((float4*)&w1s[c * 128])[lane];
#pragma unroll
        for (int s = 0; s < 5; s++) {
            float vv = vs[(wp + 8 * s) * 64 + c];
            h[s][0] += vv * w4.x;
            h[s][1] += vv * w4.y;
            h[s][2] += vv * w4.z;
            h[s][3] += vv * w4.w;
        }
    }
    float4 w2q = ((float4*)w2s)[lane];
#pragma unroll
    for (int s = 0; s < 5; s++) {
        float acc = gelu_f(h[s][0]) * w2q.x + gelu_f(h[s][1]) * w2q.y +
                    gelu_f(h[s][2]) * w2q.z + gelu_f(h[s][3]) * w2q.w;
#pragma unroll
        for (int off = 16; off; off >>= 1) acc += __shfl_xor_sync(0xffffffffu, acc, off);
        if (lane == 0) out[((size_t)(b * 512 + x)) * 40 + wp + 8 * s] = acc + b2s;
    }
}

extern "C" void kernel_launch(void* const* d_in, const int* in_sizes, int n_in,
                              void* d_out, int out_size) {
    (void)in_sizes; (void)n_in; (void)out_size;
    const float* u      = (const float*)d_in[0];
    const float* xin    = (const float*)d_in[1];
    const float* tin    = (const float*)d_in[2];
    const float* par    = (const float*)d_in[3];
    const float* fc0_w  = (const float*)d_in[4];
    const float* fc0_b  = (const float*)d_in[5];
    const float* spec_wr = (const float*)d_in[6];
    const float* spec_wi = (const float*)d_in[7];
    const float* w_conv = (const float*)d_in[8];
    const float* w_bias = (const float*)d_in[9];
    const float* fc1_w  = (const float*)d_in[10];
    const float* fc1_b  = (const float*)d_in[11];
    const float* fc2_w  = (const float*)d_in[12];
    const float* fc2_b  = (const float*)d_in[13];
    float* out = (float*)d_out;

    k_tables<<<33, 256>>>();
    k_wt<<<dim3(4, 64, 4), 256>>>(spec_wr, spec_wi);
    k_embed<<<dim3(XD, NB), 256>>>(u, xin, tin, par, fc0_w, fc0_b);
    for (int l = 0; l < 4; l++) {
        k_dft_t<<<dim3(XD, NB), 256>>>();
        k_dft_x<<<dim3(8, NB), 512>>>();
        k_mix<<<256, 256, 49152>>>(l);
        k_idft_x<<<dim3(66, NB), 256>>>();
        k_conv_inv<<<dim3(XD, NB), 256>>>(w_conv, w_bias, l, l < 3 ? 1 : 0);
    }
    k_final<<<dim3(512, NB), 256>>>(fc1_w, fc1_b, fc2_w, fc2_b, out);
}

// round 5
// speedup vs baseline: 1.0061x; 1.0061x over previous
#include <cuda_runtime.h>
#include <math.h>

#define NB 32
#define XD 521
#define TD 49
#define CW 64
#define NMODE 256
#define VROW 3136                 // TD*CW
#define V_ELEMS  52283392ull      // NB*XD*VROW
#define A_ELEMS  17072128ull      // NB*XD*16*CW
#define S_ELEMS  524288ull        // NB*NMODE*CW
#define VP_ELEMS 4194304ull       // 8*S_ELEMS
#define WT_ELEMS 4194304ull       // 4*NMODE*CW*CW

typedef unsigned long long u64;

__device__ float g_v[V_ELEMS];
__device__ float g_hr[A_ELEMS];
__device__ float g_hi[A_ELEMS];
__device__ float g_vpr[VP_ELEMS];
__device__ float g_vpi[VP_ELEMS];
__device__ float g_sr[S_ELEMS];
__device__ float g_si[S_ELEMS];
__device__ float g_wtr[WT_ELEMS];
__device__ float g_wti[WT_ELEMS];
__device__ float2 g_ett2[784];        // fwd t-twiddle, [t][kt]
__device__ float2 g_exE[16 * 521];    // (er, ei)
__device__ float2 g_exF[16 * 521];    // (-ei, er)
__device__ float2 g_exP[16 * 521];    // (er, -ei)
__device__ float2 g_exQ[16 * 521];    // (ei, er)

__device__ __forceinline__ float gelu_f(float v) {
    return 0.5f * v * (1.0f + erff(v * 0.70710678118654752f));
}
__device__ __forceinline__ u64 pk(float lo, float hi) {
    u64 r; asm("mov.b64 %0,{%1,%2};" : "=l"(r) : "f"(lo), "f"(hi)); return r;
}
__device__ __forceinline__ u64 pk1(float v) { return pk(v, v); }
__device__ __forceinline__ void fma2(u64& d, u64 a, u64 b) {
    asm("fma.rn.f32x2 %0,%1,%2,%0;" : "+l"(d) : "l"(a), "l"(b));
}
__device__ __forceinline__ float2 up2(u64 v) {
    float2 r; asm("mov.b64 {%0,%1},%2;" : "=f"(r.x), "=f"(r.y) : "l"(v)); return r;
}

// ---------- twiddle tables ----------
__global__ void k_tables() {
    int idx = blockIdx.x * blockDim.x + threadIdx.x;
    const double PI2 = 6.283185307179586476925287;
    if (idx < 784) {
        int t = idx / 16, kt = idx % 16;
        double a = -PI2 * (double)((kt * t) % 49) / 49.0;
        g_ett2[idx] = make_float2((float)cos(a), (float)sin(a));
    }
    if (idx < 8336) {
        int kx = idx / 521, x = idx % 521;
        double a = -PI2 * (double)((kx * x) % 521) / 521.0;
        float er = (float)cos(a), ei = (float)sin(a);
        g_exE[idx] = make_float2(er, ei);
        g_exF[idx] = make_float2(-ei, er);
        g_exP[idx] = make_float2(er, -ei);
        g_exQ[idx] = make_float2(ei, er);
    }
}

// ---------- spectral weight transpose: [l][i][o][m] -> [l][m][i][o] ----------
__global__ void k_wt(const float* __restrict__ wr, const float* __restrict__ wi) {
    __shared__ float sh[64 * 65];
    int mc = blockIdx.x, i = blockIdx.y, l = blockIdx.z, tid = threadIdx.x;
    size_t srcbase = ((size_t)(l * 64 + i)) * 64 * 256 + (size_t)mc * 64;
    for (int idx = tid; idx < 4096; idx += 256) {
        int o = idx >> 6, mm = idx & 63;
        sh[o * 65 + mm] = wr[srcbase + (size_t)o * 256 + mm];
    }
    __syncthreads();
    for (int idx = tid; idx < 4096; idx += 256) {
        int mm = idx >> 6, o = idx & 63;
        g_wtr[(((size_t)(l * 256 + mc * 64 + mm)) * 64 + i) * 64 + o] = sh[o * 65 + mm];
    }
    __syncthreads();
    for (int idx = tid; idx < 4096; idx += 256) {
        int o = idx >> 6, mm = idx & 63;
        sh[o * 65 + mm] = wi[srcbase + (size_t)o * 256 + mm];
    }
    __syncthreads();
    for (int idx = tid; idx < 4096; idx += 256) {
        int mm = idx >> 6, o = idx & 63;
        g_wti[(((size_t)(l * 256 + mc * 64 + mm)) * 64 + i) * 64 + o] = sh[o * 65 + mm];
    }
}

// ---------- embed (fc0) fused with forward t-DFT; 4 x per block ----------
__global__ void __launch_bounds__(256) k_embed(const float* __restrict__ u,
                                               const float* __restrict__ xin,
                                               const float* __restrict__ tin,
                                               const float* __restrict__ par,
                                               const float* __restrict__ w0,
                                               const float* __restrict__ b0) {
    __shared__ __align__(16) float vsm[4 * 2560];
    __shared__ float2 etts[640];
    __shared__ float feat[4][16];
    __shared__ float tv[40];
    int xq = blockIdx.x, b = blockIdx.y, tid = threadIdx.x;
    int xh = tid >> 6, c = tid & 63;
    int x = xq * 4 + xh;
    for (int i = tid; i < 640; i += 256) etts[i] = g_ett2[i];
    if (tid < 40) tv[tid] = tin[b * 40 + tid];
    if (c < 13 && x < 512) {
        float f;
        if (c < 10) f = u[((size_t)(b * 512 + x)) * 10 + c];
        else if (c < 12) f = par[b * 2 + c - 10];
        else f = xin[b * 512 + x];
        feat[xh][c] = f;
    }
    __syncthreads();
    bool vx = (x < 512);
    size_t vb = ((size_t)(b * XD + x)) * VROW;
    float basev = 0.f, w13c = 0.f;
    if (vx) {
        basev = b0[c];
#pragma unroll
        for (int k = 0; k < 13; k++) basev += feat[xh][k] * w0[k * 64 + c];
        w13c = w0[13 * 64 + c];
    }
    float* vrow = vsm + xh * 2560;
    for (int t = 0; t < 40; t++) {
        float val = vx ? fmaf(tv[t], w13c, basev) : 0.f;
        vrow[t * 64 + c] = val;
        if (x < XD) g_v[vb + t * 64 + c] = val;
    }
    if (x < XD)
        for (int t = 40; t < 49; t++) g_v[vb + t * 64 + c] = 0.f;
    __syncthreads();
    // phase 2: t-DFT, each thread: 16 channel-quad cg, 4 kt values
    int cg = tid & 15, ktp = (tid >> 4) & 3, xh2 = tid >> 6;
    int x2 = xq * 4 + xh2;
    const ulonglong2* vp = (const ulonglong2*)(vsm + xh2 * 2560);
    u64 Ar[4][2], Ai[4][2];
#pragma unroll
    for (int j = 0; j < 4; j++) { Ar[j][0] = Ar[j][1] = Ai[j][0] = Ai[j][1] = 0ull; }
    for (int t = 0; t < 40; t++) {
        ulonglong2 v2 = vp[t * 16 + cg];
#pragma unroll
        for (int j = 0; j < 4; j++) {
            float2 e = etts[t * 16 + ktp + j * 4];
            u64 er2 = pk1(e.x), ei2 = pk1(e.y);
            fma2(Ar[j][0], v2.x, er2); fma2(Ar[j][1], v2.y, er2);
            fma2(Ai[j][0], v2.x, ei2); fma2(Ai[j][1], v2.y, ei2);
        }
    }
    if (x2 < XD) {
        size_t ab = ((size_t)(b * XD + x2)) * 16;
#pragma unroll
        for (int j = 0; j < 4; j++) {
            int kt = ktp + j * 4;
            float2 r0 = up2(Ar[j][0]), r1 = up2(Ar[j][1]);
            float2 i0 = up2(Ai[j][0]), i1 = up2(Ai[j][1]);
            ((float4*)(g_hr + (ab + kt) * 64))[cg] = make_float4(r0.x, r0.y, r1.x, r1.y);
            ((float4*)(g_hi + (ab + kt) * 64))[cg] = make_float4(i0.x, i0.y, i1.x, i1.y);
        }
    }
}

// ---------- forward DFT over x (8 partial chunks, f32x2) ----------
__global__ void __launch_bounds__(512) k_dft_x() {
    __shared__ float2 E_s[16 * 66], F_s[16 * 66];
    int p = blockIdx.x, b = blockIdx.y, tid = threadIdx.x;
    int xs = p * 66;
    int cnt = min(66, XD - xs);
    for (int i = tid; i < 16 * 66; i += 512) {
        int kx = i / 66, xl = i % 66;
        if (xl < cnt) {
            E_s[i] = g_exE[kx * 521 + xs + xl];
            F_s[i] = g_exF[kx * 521 + xs + xl];
        }
    }
    __syncthreads();
    int c = tid & 63, kp = tid >> 6;
    int kt0 = kp * 2;
    u64 V0[16], V1[16];
#pragma unroll
    for (int kx = 0; kx < 16; kx++) { V0[kx] = 0ull; V1[kx] = 0ull; }
    for (int xl = 0; xl < cnt; xl++) {
        size_t base = ((size_t)(b * XD + xs + xl)) * 16;
        float a0r = g_hr[(base + kt0) * 64 + c], a0i = g_hi[(base + kt0) * 64 + c];
        float a1r = g_hr[(base + kt0 + 1) * 64 + c], a1i = g_hi[(base + kt0 + 1) * 64 + c];
        u64 r0 = pk1(a0r), i0 = pk1(a0i), r1 = pk1(a1r), i1 = pk1(a1i);
#pragma unroll
        for (int kx = 0; kx < 16; kx++) {
            u64 E = *(const u64*)&E_s[kx * 66 + xl];
            u64 F = *(const u64*)&F_s[kx * 66 + xl];
            fma2(V0[kx], r0, E); fma2(V0[kx], i0, F);
            fma2(V1[kx], r1, E); fma2(V1[kx], i1, F);
        }
    }
    size_t ob = ((size_t)(p * 32 + b)) * NMODE * 64;
#pragma unroll
    for (int kx = 0; kx < 16; kx++) {
        float2 v0 = up2(V0[kx]), v1 = up2(V1[kx]);
        g_vpr[ob + (kx * 16 + kt0) * 64 + c] = v0.x;
        g_vpi[ob + (kx * 16 + kt0) * 64 + c] = v0.y;
        g_vpr[ob + (kx * 16 + kt0 + 1) * 64 + c] = v1.x;
        g_vpi[ob + (kx * 16 + kt0 + 1) * 64 + c] = v1.y;
    }
}

// ---------- per-mode complex channel mix ----------
__global__ void __launch_bounds__(256) k_mix(int l) {
    extern __shared__ float sh[];
    float* wr_sh = sh;
    float* wi_sh = sh + 4096;
    float* vrs = sh + 8192;
    float* vis = sh + 10240;
    int m = blockIdx.x, tid = threadIdx.x;
    size_t wb = ((size_t)(l * 256 + m)) * 4096;
    for (int i = tid; i < 4096; i += 256) {
        wr_sh[i] = g_wtr[wb + i];
        wi_sh[i] = g_wti[wb + i];
    }
    for (int i = tid; i < 2048; i += 256) {
        int bb = i >> 6, c = i & 63;
        size_t o = (((size_t)bb) * NMODE + m) * 64 + c;
        float sr = 0.f, si = 0.f;
#pragma unroll
        for (int pp = 0; pp < 8; pp++) {
            sr += g_vpr[(size_t)pp * S_ELEMS + o];
            si += g_vpi[(size_t)pp * S_ELEMS + o];
        }
        vrs[i] = sr;
        vis[i] = si;
    }
    __syncthreads();
    int o = tid & 63, bg = tid >> 6;
    for (int bb = bg; bb < 32; bb += 4) {
        u64 S = 0ull;   // (sr, si)
#pragma unroll
        for (int c = 0; c < 64; c++) {
            float vr = vrs[bb * 64 + c], vi = vis[bb * 64 + c];
            float wr = wr_sh[c * 64 + o], wi = wi_sh[c * 64 + o];
            u64 W1 = pk(wr, wi), W2 = pk(-wi, wr);
            fma2(S, pk1(vr), W1); fma2(S, pk1(vi), W2);
        }
        float2 s2 = up2(S);
        size_t ob = (((size_t)bb) * NMODE + m) * 64 + o;
        g_sr[ob] = s2.x;
        g_si[ob] = s2.y;
    }
}

// ---------- inverse DFT over x (f32x2) ----------
__global__ void __launch_bounds__(256) k_idft_x() {
    __shared__ float ssr[1024], ssi[1024];
    int xc = blockIdx.x, b = blockIdx.y, tid = threadIdx.x;
    int lane = tid & 31, wp = tid >> 5;
    int x = xc * 8 + wp;
    bool valid = (x < XD);
    u64 H0[16], H1[16];  // (hr, hi)
#pragma unroll
    for (int kt = 0; kt < 16; kt++) { H0[kt] = 0ull; H1[kt] = 0ull; }
    for (int kx = 0; kx < 16; kx++) {
        __syncthreads();
        size_t sb = (((size_t)b) * NMODE + kx * 16) * 64;
        for (int i = tid; i < 1024; i += 256) {
            ssr[i] = g_sr[sb + i];
            ssi[i] = g_si[sb + i];
        }
        __syncthreads();
        if (valid) {
            float2 Pv = g_exP[kx * 521 + x], Qv = g_exQ[kx * 521 + x];
            u64 P = *(u64*)&Pv, Q = *(u64*)&Qv;
#pragma unroll
            for (int kt = 0; kt < 16; kt++) {
                u64 s0r = pk1(ssr[kt * 64 + lane]), s0i = pk1(ssi[kt * 64 + lane]);
                u64 s1r = pk1(ssr[kt * 64 + lane + 32]), s1i = pk1(ssi[kt * 64 + lane + 32]);
                fma2(H0[kt], s0r, P); fma2(H0[kt], s0i, Q);
                fma2(H1[kt], s1r, P); fma2(H1[kt], s1i, Q);
            }
        }
    }
    if (valid) {
        size_t hb = ((size_t)(b * XD + x)) * 1024;
#pragma unroll
        for (int kt = 0; kt < 16; kt++) {
            float2 h0 = up2(H0[kt]), h1 = up2(H1[kt]);
            g_hr[hb + kt * 64 + lane] = h0.x;
            g_hi[hb + kt * 64 + lane] = h0.y;
            g_hr[hb + kt * 64 + lane + 32] = h1.x;
            g_hi[hb + kt * 64 + lane + 32] = h1.y;
        }
    }
}

// ---------- fused: inverse-t DFT + pointwise conv + bias + gelu + fwd t-DFT ----------
__global__ void __launch_bounds__(256) k_conv_inv(const float* __restrict__ wconv,
                                                  const float* __restrict__ wbias,
                                                  int l, int last) {
    __shared__ __align__(16) float v_sh[3328];
    __shared__ __align__(16) float wT[4096];
    __shared__ __align__(16) float hrs[1024], his[1024];
    __shared__ float2 ett_s[832];
    __shared__ __align__(16) float bsh[64];
    int x = blockIdx.x, b = blockIdx.y, tid = threadIdx.x;
    size_t vb = ((size_t)(b * XD + x)) * VROW;
    for (int i = tid; i < 784; i += 256) ((float4*)v_sh)[i] = ((const float4*)(g_v + vb))[i];
    for (int i = 3136 + tid; i < 3328; i += 256) v_sh[i] = 0.f;
    for (int i = tid; i < 4096; i += 256) {
        int o = i >> 6, c = i & 63;
        wT[c * 64 + o] = wconv[l * 4096 + i];
    }
    const float invXT = 1.f / (521.f * 49.f);
    size_t hb = ((size_t)(b * XD + x)) * 1024;
    for (int i = tid; i < 1024; i += 256) {
        float sc = (i >= 64 ? 2.f : 1.f) * invXT;
        hrs[i] = g_hr[hb + i] * sc;
        his[i] = g_hi[hb + i] * sc;
    }
    for (int i = tid; i < 832; i += 256)
        ett_s[i] = (i < 784) ? g_ett2[i] : make_float2(0.f, 0.f);
    if (tid < 64) bsh[tid] = wbias[l * 64 + tid];
    __syncthreads();

    int og = tid & 15, tg = tid >> 4;
    int t0 = tg * 4;
    u64 A[4][2];
    if (t0 < 49) {
        ulonglong2 b2 = ((const ulonglong2*)bsh)[og];
#pragma unroll
        for (int tt = 0; tt < 4; tt++) { A[tt][0] = b2.x; A[tt][1] = b2.y; }
        const ulonglong2* wp = (const ulonglong2*)wT;
#pragma unroll 8
        for (int c = 0; c < 64; c++) {
            ulonglong2 w2 = wp[c * 16 + og];
            u64 v0 = pk1(v_sh[(t0 + 0) * 64 + c]);
            u64 v1 = pk1(v_sh[(t0 + 1) * 64 + c]);
            u64 v2 = pk1(v_sh[(t0 + 2) * 64 + c]);
            u64 v3 = pk1(v_sh[(t0 + 3) * 64 + c]);
            fma2(A[0][0], w2.x, v0); fma2(A[0][1], w2.y, v0);
            fma2(A[1][0], w2.x, v1); fma2(A[1][1], w2.y, v1);
            fma2(A[2][0], w2.x, v2); fma2(A[2][1], w2.y, v2);
            fma2(A[3][0], w2.x, v3); fma2(A[3][1], w2.y, v3);
        }
        const ulonglong2* hrp = (const ulonglong2*)hrs;
        const ulonglong2* hip = (const ulonglong2*)his;
#pragma unroll
        for (int kt = 0; kt < 16; kt++) {
            ulonglong2 HR = hrp[kt * 16 + og];
            ulonglong2 HI = hip[kt * 16 + og];
#pragma unroll
            for (int tt = 0; tt < 4; tt++) {
                float2 e = ett_s[(t0 + tt) * 16 + kt];
                u64 er2 = pk1(e.x), ei2 = pk1(e.y);
                fma2(A[tt][0], HR.x, er2); fma2(A[tt][0], HI.x, ei2);
                fma2(A[tt][1], HR.y, er2); fma2(A[tt][1], HI.y, ei2);
            }
        }
    }
    __syncthreads();
    if (t0 < 49) {
#pragma unroll
        for (int tt = 0; tt < 4; tt++) {
            int t = t0 + tt;
            if (t < 49) {
                float2 lo = up2(A[tt][0]), hi = up2(A[tt][1]);
                float4 f4;
                if (!last) {
                    f4 = make_float4(gelu_f(lo.x), gelu_f(lo.y), gelu_f(hi.x), gelu_f(hi.y));
                    ((float4*)v_sh)[t * 16 + og] = f4;
                } else {
                    f4 = make_float4(lo.x, lo.y, hi.x, hi.y);
                    ((float4*)(g_v + vb))[t * 16 + og] = f4;
                }
            }
        }
    }
    __syncthreads();
    if (!last) {
        if (tid < 64) {
            int cg = tid & 15, ktp = tid >> 4;
            const ulonglong2* vp = (const ulonglong2*)v_sh;
            u64 Ar[4][2], Ai[4][2];
#pragma unroll
            for (int j = 0; j < 4; j++) { Ar[j][0] = Ar[j][1] = Ai[j][0] = Ai[j][1] = 0ull; }
            for (int t = 0; t < 49; t++) {
                ulonglong2 v2 = vp[t * 16 + cg];
#pragma unroll
                for (int j = 0; j < 4; j++) {
                    float2 e = ett_s[t * 16 + ktp + j * 4];
                    u64 er2 = pk1(e.x), ei2 = pk1(e.y);
                    fma2(Ar[j][0], v2.x, er2); fma2(Ar[j][1], v2.y, er2);
                    fma2(Ai[j][0], v2.x, ei2); fma2(Ai[j][1], v2.y, ei2);
                }
            }
            size_t ab = ((size_t)(b * XD + x)) * 16;
#pragma unroll
            for (int j = 0; j < 4; j++) {
                int kt = ktp + j * 4;
                float2 r0 = up2(Ar[j][0]), r1 = up2(Ar[j][1]);
                float2 i0 = up2(Ai[j][0]), i1 = up2(Ai[j][1]);
                ((float4*)(g_hr + (ab + kt) * 64))[cg] = make_float4(r0.x, r0.y, r1.x, r1.y);
                ((float4*)(g_hi + (ab + kt) * 64))[cg] = make_float4(i0.x, i0.y, i1.x, i1.y);
            }
        } else {
            for (int i = tid - 64; i < 784; i += 192)
                ((float4*)(g_v + vb))[i] = ((const float4*)v_sh)[i];
        }
    }
}

// ---------- crop + fc1 + gelu + fc2 (f32x2) ----------
__global__ void __launch_bounds__(256) k_final(const float* __restrict__ w1,
                                               const float* __restrict__ b1,
                                               const float* __restrict__ w2,
                                               const float* __restrict__ b2,
                                               float* __restrict__ out) {
    __shared__ __align__(16) float w1s[64 * 128];
    __shared__ __align__(16) float vs[40 * 64];
    __shared__ __align__(16) float b1s[128], w2s[128];
    __shared__ float b2s;
    int x = blockIdx.x, b = blockIdx.y, tid = threadIdx.x;
    for (int i = tid; i < 8192; i += 256) w1s[i] = w1[i];
    if (tid < 128) { b1s[tid] = b1[tid]; w2s[tid] = w2[tid]; }
    if (tid == 0) b2s = b2[0];
    size_t vb = ((size_t)(b * XD + x)) * VROW;
    for (int i = tid; i < 640; i += 256) ((float4*)vs)[i] = ((const float4*)(g_v + vb))[i];
    __syncthreads();
    int lane = tid & 31, wp = tid >> 5;
    u64 H[5][2];
    ulonglong2 bq = ((const ulonglong2*)b1s)[lane];
#pragma unroll
    for (int s = 0; s < 5; s++) { H[s][0] = bq.x; H[s][1] = bq.y; }
    const ulonglong2* w1p = (const ulonglong2*)w1s;
#pragma unroll 4
    for (int c = 0; c < 64; c++) {
        ulonglong2 w2v = w1p[c * 32 + lane];
#pragma unroll
        for (int s = 0; s < 5; s++) {
            u64 vv = pk1(vs[(wp + 8 * s) * 64 + c]);
            fma2(H[s][0], w2v.x, vv);
            fma2(H[s][1], w2v.y, vv);
        }
    }
    float4 w2q = ((const float4*)w2s)[lane];
#pragma unroll
    for (int s = 0; s < 5; s++) {
        float2 hlo = up2(H[s][0]), hhi = up2(H[s][1]);
        float acc = gelu_f(hlo.x) * w2q.x + gelu_f(hlo.y) * w2q.y +
                    gelu_f(hhi.x) * w2q.z + gelu_f(hhi.y) * w2q.w;
#pragma unroll
        for (int off = 16; off; off >>= 1) acc += __shfl_xor_sync(0xffffffffu, acc, off);
        if (lane == 0) out[((size_t)(b * 512 + x)) * 40 + wp + 8 * s] = acc + b2s;
    }
}

extern "C" void kernel_launch(void* const* d_in, const int* in_sizes, int n_in,
                              void* d_out, int out_size) {
    (void)in_sizes; (void)n_in; (void)out_size;
    const float* u      = (const float*)d_in[0];
    const float* xin    = (const float*)d_in[1];
    const float* tin    = (const float*)d_in[2];
    const float* par    = (const float*)d_in[3];
    const float* fc0_w  = (const float*)d_in[4];
    const float* fc0_b  = (const float*)d_in[5];
    const float* spec_wr = (const float*)d_in[6];
    const float* spec_wi = (const float*)d_in[7];
    const float* w_conv = (const float*)d_in[8];
    const float* w_bias = (const float*)d_in[9];
    const float* fc1_w  = (const float*)d_in[10];
    const float* fc1_b  = (const float*)d_in[11];
    const float* fc2_w  = (const float*)d_in[12];
    const float* fc2_b  = (const float*)d_in[13];
    float* out = (float*)d_out;

    k_tables<<<33, 256>>>();
    k_wt<<<dim3(4, 64, 4), 256>>>(spec_wr, spec_wi);
    k_embed<<<dim3(131, NB), 256>>>(u, xin, tin, par, fc0_w, fc0_b);
    for (int l = 0; l < 4; l++) {
        k_dft_x<<<dim3(8, NB), 512>>>();
        k_mix<<<256, 256, 49152>>>(l);
        k_idft_x<<<dim3(66, NB), 256>>>();
        k_conv_inv<<<dim3(XD, NB), 256>>>(w_conv, w_bias, l, l == 3 ? 1 : 0);
    }
    k_final<<<dim3(512, NB), 256>>>(fc1_w, fc1_b, fc2_w, fc2_b, out);
}

// round 6
// speedup vs baseline: 1.0709x; 1.0644x over previous
#include <cuda_runtime.h>
#include <math.h>

#define NB 32
#define XD 521
#define TD 49
#define CW 64
#define NMODE 256
#define VROW 3136                 // TD*CW
#define V_ELEMS  52283392ull      // NB*XD*VROW
#define A_ELEMS  17072128ull      // NB*XD*16*CW
#define S_ELEMS  524288ull        // NB*NMODE*CW
#define VP_ELEMS 4194304ull       // 8*S_ELEMS
#define WT_ELEMS 4194304ull       // 4*NMODE*CW*CW

typedef unsigned long long u64;

__device__ float g_v[V_ELEMS];
__device__ float g_hr[A_ELEMS];
__device__ float g_hi[A_ELEMS];
__device__ float g_vpr[VP_ELEMS];
__device__ float g_vpi[VP_ELEMS];
__device__ float g_sr[S_ELEMS];
__device__ float g_si[S_ELEMS];
__device__ float g_wtr[WT_ELEMS];
__device__ float g_wti[WT_ELEMS];
__device__ float2 g_ett2[784];        // fwd t-twiddle, [t][kt]
__device__ float2 g_exE[16 * 521];    // (er, ei)
__device__ float2 g_exF[16 * 521];    // (-ei, er)
__device__ float2 g_exP[16 * 521];    // (er, -ei)
__device__ float2 g_exQ[16 * 521];    // (ei, er)

__device__ __forceinline__ float gelu_f(float v) {
    return 0.5f * v * (1.0f + erff(v * 0.70710678118654752f));
}
__device__ __forceinline__ u64 pk(float lo, float hi) {
    u64 r; asm("mov.b64 %0,{%1,%2};" : "=l"(r) : "f"(lo), "f"(hi)); return r;
}
__device__ __forceinline__ u64 pk1(float v) { return pk(v, v); }
__device__ __forceinline__ void fma2(u64& d, u64 a, u64 b) {
    asm("fma.rn.f32x2 %0,%1,%2,%0;" : "+l"(d) : "l"(a), "l"(b));
}
__device__ __forceinline__ float2 up2(u64 v) {
    float2 r; asm("mov.b64 {%0,%1},%2;" : "=f"(r.x), "=f"(r.y) : "l"(v)); return r;
}

// ---------- twiddle tables ----------
__global__ void k_tables() {
    int idx = blockIdx.x * blockDim.x + threadIdx.x;
    const double PI2 = 6.283185307179586476925287;
    if (idx < 784) {
        int t = idx / 16, kt = idx % 16;
        double a = -PI2 * (double)((kt * t) % 49) / 49.0;
        g_ett2[idx] = make_float2((float)cos(a), (float)sin(a));
    }
    if (idx < 8336) {
        int kx = idx / 521, x = idx % 521;
        double a = -PI2 * (double)((kx * x) % 521) / 521.0;
        float er = (float)cos(a), ei = (float)sin(a);
        g_exE[idx] = make_float2(er, ei);
        g_exF[idx] = make_float2(-ei, er);
        g_exP[idx] = make_float2(er, -ei);
        g_exQ[idx] = make_float2(ei, er);
    }
}

// ---------- spectral weight transpose: [l][i][o][m] -> [l][m][i][o] ----------
__global__ void k_wt(const float* __restrict__ wr, const float* __restrict__ wi) {
    __shared__ float sh[64 * 65];
    int mc = blockIdx.x, i = blockIdx.y, l = blockIdx.z, tid = threadIdx.x;
    size_t srcbase = ((size_t)(l * 64 + i)) * 64 * 256 + (size_t)mc * 64;
    for (int idx = tid; idx < 4096; idx += 256) {
        int o = idx >> 6, mm = idx & 63;
        sh[o * 65 + mm] = wr[srcbase + (size_t)o * 256 + mm];
    }
    __syncthreads();
    for (int idx = tid; idx < 4096; idx += 256) {
        int mm = idx >> 6, o = idx & 63;
        g_wtr[(((size_t)(l * 256 + mc * 64 + mm)) * 64 + i) * 64 + o] = sh[o * 65 + mm];
    }
    __syncthreads();
    for (int idx = tid; idx < 4096; idx += 256) {
        int o = idx >> 6, mm = idx & 63;
        sh[o * 65 + mm] = wi[srcbase + (size_t)o * 256 + mm];
    }
    __syncthreads();
    for (int idx = tid; idx < 4096; idx += 256) {
        int mm = idx >> 6, o = idx & 63;
        g_wti[(((size_t)(l * 256 + mc * 64 + mm)) * 64 + i) * 64 + o] = sh[o * 65 + mm];
    }
}

// ---------- embed (fc0) fused with forward t-DFT; 4 x per block ----------
__global__ void __launch_bounds__(256) k_embed(const float* __restrict__ u,
                                               const float* __restrict__ xin,
                                               const float* __restrict__ tin,
                                               const float* __restrict__ par,
                                               const float* __restrict__ w0,
                                               const float* __restrict__ b0) {
    __shared__ __align__(16) float vsm[4 * 2560];
    __shared__ float2 etts[640];
    __shared__ float feat[4][16];
    __shared__ float tv[40];
    int xq = blockIdx.x, b = blockIdx.y, tid = threadIdx.x;
    int xh = tid >> 6, c = tid & 63;
    int x = xq * 4 + xh;
    for (int i = tid; i < 640; i += 256) etts[i] = g_ett2[i];
    if (tid < 40) tv[tid] = tin[b * 40 + tid];
    if (c < 13 && x < 512) {
        float f;
        if (c < 10) f = u[((size_t)(b * 512 + x)) * 10 + c];
        else if (c < 12) f = par[b * 2 + c - 10];
        else f = xin[b * 512 + x];
        feat[xh][c] = f;
    }
    __syncthreads();
    bool vx = (x < 512);
    size_t vb = ((size_t)(b * XD + x)) * VROW;
    float basev = 0.f, w13c = 0.f;
    if (vx) {
        basev = b0[c];
#pragma unroll
        for (int k = 0; k < 13; k++) basev += feat[xh][k] * w0[k * 64 + c];
        w13c = w0[13 * 64 + c];
    }
    float* vrow = vsm + xh * 2560;
    for (int t = 0; t < 40; t++) {
        float val = vx ? fmaf(tv[t], w13c, basev) : 0.f;
        vrow[t * 64 + c] = val;
        if (x < XD) g_v[vb + t * 64 + c] = val;
    }
    if (x < XD)
        for (int t = 40; t < 49; t++) g_v[vb + t * 64 + c] = 0.f;
    __syncthreads();
    // phase 2: t-DFT, each thread: 16 channel-quad cg, 4 kt values
    int cg = tid & 15, ktp = (tid >> 4) & 3, xh2 = tid >> 6;
    int x2 = xq * 4 + xh2;
    const ulonglong2* vp = (const ulonglong2*)(vsm + xh2 * 2560);
    u64 Ar[4][2], Ai[4][2];
#pragma unroll
    for (int j = 0; j < 4; j++) { Ar[j][0] = Ar[j][1] = Ai[j][0] = Ai[j][1] = 0ull; }
    for (int t = 0; t < 40; t++) {
        ulonglong2 v2 = vp[t * 16 + cg];
#pragma unroll
        for (int j = 0; j < 4; j++) {
            float2 e = etts[t * 16 + ktp + j * 4];
            u64 er2 = pk1(e.x), ei2 = pk1(e.y);
            fma2(Ar[j][0], v2.x, er2); fma2(Ar[j][1], v2.y, er2);
            fma2(Ai[j][0], v2.x, ei2); fma2(Ai[j][1], v2.y, ei2);
        }
    }
    if (x2 < XD) {
        size_t ab = ((size_t)(b * XD + x2)) * 16;
#pragma unroll
        for (int j = 0; j < 4; j++) {
            int kt = ktp + j * 4;
            float2 r0 = up2(Ar[j][0]), r1 = up2(Ar[j][1]);
            float2 i0 = up2(Ai[j][0]), i1 = up2(Ai[j][1]);
            ((float4*)(g_hr + (ab + kt) * 64))[cg] = make_float4(r0.x, r0.y, r1.x, r1.y);
            ((float4*)(g_hi + (ab + kt) * 64))[cg] = make_float4(i0.x, i0.y, i1.x, i1.y);
        }
    }
}

// ---------- forward DFT over x: 8 x-chunks x 2 kt-halves, 256 threads ----------
__global__ void __launch_bounds__(256) k_dft_x() {
    __shared__ float2 E_s[16 * 66], F_s[16 * 66];
    int p = blockIdx.x, kth = blockIdx.y, b = blockIdx.z, tid = threadIdx.x;
    int xs = p * 66;
    int cnt = min(66, XD - xs);
    for (int i = tid; i < 16 * 66; i += 256) {
        int kx = i / 66, xl = i % 66;
        if (xl < cnt) {
            E_s[i] = g_exE[kx * 521 + xs + xl];
            F_s[i] = g_exF[kx * 521 + xs + xl];
        }
    }
    __syncthreads();
    int c = tid & 63, kp = tid >> 6;       // kp 0..3
    int kt0 = kth * 8 + kp * 2;
    u64 V0[16], V1[16];
#pragma unroll
    for (int kx = 0; kx < 16; kx++) { V0[kx] = 0ull; V1[kx] = 0ull; }
    for (int xl = 0; xl < cnt; xl++) {
        size_t base = ((size_t)(b * XD + xs + xl)) * 16;
        float a0r = g_hr[(base + kt0) * 64 + c], a0i = g_hi[(base + kt0) * 64 + c];
        float a1r = g_hr[(base + kt0 + 1) * 64 + c], a1i = g_hi[(base + kt0 + 1) * 64 + c];
        u64 r0 = pk1(a0r), i0 = pk1(a0i), r1 = pk1(a1r), i1 = pk1(a1i);
#pragma unroll
        for (int kx = 0; kx < 16; kx++) {
            u64 E = *(const u64*)&E_s[kx * 66 + xl];
            u64 F = *(const u64*)&F_s[kx * 66 + xl];
            fma2(V0[kx], r0, E); fma2(V0[kx], i0, F);
            fma2(V1[kx], r1, E); fma2(V1[kx], i1, F);
        }
    }
    size_t ob = ((size_t)(p * 32 + b)) * NMODE * 64;
#pragma unroll
    for (int kx = 0; kx < 16; kx++) {
        float2 v0 = up2(V0[kx]), v1 = up2(V1[kx]);
        g_vpr[ob + (kx * 16 + kt0) * 64 + c] = v0.x;
        g_vpi[ob + (kx * 16 + kt0) * 64 + c] = v0.y;
        g_vpr[ob + (kx * 16 + kt0 + 1) * 64 + c] = v1.x;
        g_vpi[ob + (kx * 16 + kt0 + 1) * 64 + c] = v1.y;
    }
}

// ---------- per-mode complex channel mix (batch-split) ----------
__global__ void __launch_bounds__(256) k_mix(int l) {
    extern __shared__ float sh[];
    float* wr_sh = sh;            // 4096
    float* wi_sh = sh + 4096;     // 4096
    float* vrs = sh + 8192;       // 1024
    float* vis = sh + 9216;       // 1024
    int m = blockIdx.x, bh = blockIdx.y, tid = threadIdx.x;
    size_t wb = ((size_t)(l * 256 + m)) * 4096;
    for (int i = tid; i < 4096; i += 256) {
        wr_sh[i] = g_wtr[wb + i];
        wi_sh[i] = g_wti[wb + i];
    }
    for (int i = tid; i < 1024; i += 256) {
        int bb = (i >> 6) + bh * 16, c = i & 63;
        size_t o = (((size_t)bb) * NMODE + m) * 64 + c;
        float sr = 0.f, si = 0.f;
#pragma unroll
        for (int pp = 0; pp < 8; pp++) {
            sr += g_vpr[(size_t)pp * S_ELEMS + o];
            si += g_vpi[(size_t)pp * S_ELEMS + o];
        }
        vrs[i] = sr;
        vis[i] = si;
    }
    __syncthreads();
    int o = tid & 63, bg = tid >> 6;
    for (int bbl = bg; bbl < 16; bbl += 4) {
        u64 S = 0ull;   // (sr, si)
#pragma unroll
        for (int c = 0; c < 64; c++) {
            float vr = vrs[bbl * 64 + c], vi = vis[bbl * 64 + c];
            float wr = wr_sh[c * 64 + o], wi = wi_sh[c * 64 + o];
            u64 W1 = pk(wr, wi), W2 = pk(-wi, wr);
            fma2(S, pk1(vr), W1); fma2(S, pk1(vi), W2);
        }
        float2 s2 = up2(S);
        size_t ob = (((size_t)(bh * 16 + bbl)) * NMODE + m) * 64 + o;
        g_sr[ob] = s2.x;
        g_si[ob] = s2.y;
    }
}

// ---------- inverse DFT over x (f32x2) ----------
__global__ void __launch_bounds__(256) k_idft_x() {
    __shared__ float ssr[1024], ssi[1024];
    int xc = blockIdx.x, b = blockIdx.y, tid = threadIdx.x;
    int lane = tid & 31, wp = tid >> 5;
    int x = xc * 8 + wp;
    bool valid = (x < XD);
    u64 H0[16], H1[16];  // (hr, hi)
#pragma unroll
    for (int kt = 0; kt < 16; kt++) { H0[kt] = 0ull; H1[kt] = 0ull; }
    for (int kx = 0; kx < 16; kx++) {
        __syncthreads();
        size_t sb = (((size_t)b) * NMODE + kx * 16) * 64;
        for (int i = tid; i < 1024; i += 256) {
            ssr[i] = g_sr[sb + i];
            ssi[i] = g_si[sb + i];
        }
        __syncthreads();
        if (valid) {
            float2 Pv = g_exP[kx * 521 + x], Qv = g_exQ[kx * 521 + x];
            u64 P = *(u64*)&Pv, Q = *(u64*)&Qv;
#pragma unroll
            for (int kt = 0; kt < 16; kt++) {
                u64 s0r = pk1(ssr[kt * 64 + lane]), s0i = pk1(ssi[kt * 64 + lane]);
                u64 s1r = pk1(ssr[kt * 64 + lane + 32]), s1i = pk1(ssi[kt * 64 + lane + 32]);
                fma2(H0[kt], s0r, P); fma2(H0[kt], s0i, Q);
                fma2(H1[kt], s1r, P); fma2(H1[kt], s1i, Q);
            }
        }
    }
    if (valid) {
        size_t hb = ((size_t)(b * XD + x)) * 1024;
#pragma unroll
        for (int kt = 0; kt < 16; kt++) {
            float2 h0 = up2(H0[kt]), h1 = up2(H1[kt]);
            g_hr[hb + kt * 64 + lane] = h0.x;
            g_hi[hb + kt * 64 + lane] = h0.y;
            g_hr[hb + kt * 64 + lane + 32] = h1.x;
            g_hi[hb + kt * 64 + lane + 32] = h1.y;
        }
    }
}

// ---------- fused: inverse-t DFT + pointwise conv + bias + gelu + fwd t-DFT ----------
__global__ void __launch_bounds__(256) k_conv_inv(const float* __restrict__ wconv,
                                                  const float* __restrict__ wbias,
                                                  int l, int last) {
    __shared__ __align__(16) float v_sh[3328];
    __shared__ __align__(16) float wT[4096];
    __shared__ __align__(16) float hrs[1024], his[1024];
    __shared__ float2 ett_s[832];
    __shared__ __align__(16) float bsh[64];
    int x = blockIdx.x, b = blockIdx.y, tid = threadIdx.x;
    size_t vb = ((size_t)(b * XD + x)) * VROW;
    for (int i = tid; i < 784; i += 256) ((float4*)v_sh)[i] = ((const float4*)(g_v + vb))[i];
    for (int i = 3136 + tid; i < 3328; i += 256) v_sh[i] = 0.f;
    for (int i = tid; i < 4096; i += 256) {
        int o = i >> 6, c = i & 63;
        wT[c * 64 + o] = wconv[l * 4096 + i];
    }
    const float invXT = 1.f / (521.f * 49.f);
    size_t hb = ((size_t)(b * XD + x)) * 1024;
    for (int i = tid; i < 1024; i += 256) {
        float sc = (i >= 64 ? 2.f : 1.f) * invXT;
        hrs[i] = g_hr[hb + i] * sc;
        his[i] = g_hi[hb + i] * sc;
    }
    for (int i = tid; i < 832; i += 256)
        ett_s[i] = (i < 784) ? g_ett2[i] : make_float2(0.f, 0.f);
    if (tid < 64) bsh[tid] = wbias[l * 64 + tid];
    __syncthreads();

    int og = tid & 15, tg = tid >> 4;
    int t0 = tg * 4;
    u64 A[4][2];
    if (t0 < 49) {
        ulonglong2 b2 = ((const ulonglong2*)bsh)[og];
#pragma unroll
        for (int tt = 0; tt < 4; tt++) { A[tt][0] = b2.x; A[tt][1] = b2.y; }
        const ulonglong2* wp = (const ulonglong2*)wT;
        const float4* v4p = (const float4*)v_sh;
#pragma unroll 4
        for (int cq = 0; cq < 16; cq++) {
            float4 v0 = v4p[(t0 + 0) * 16 + cq];
            float4 v1 = v4p[(t0 + 1) * 16 + cq];
            float4 v2 = v4p[(t0 + 2) * 16 + cq];
            float4 v3 = v4p[(t0 + 3) * 16 + cq];
            ulonglong2 wa = wp[(cq * 4 + 0) * 16 + og];
            ulonglong2 wb2 = wp[(cq * 4 + 1) * 16 + og];
            ulonglong2 wc = wp[(cq * 4 + 2) * 16 + og];
            ulonglong2 wd = wp[(cq * 4 + 3) * 16 + og];
            u64 p0, p1, p2, p3;
            p0 = pk1(v0.x); p1 = pk1(v1.x); p2 = pk1(v2.x); p3 = pk1(v3.x);
            fma2(A[0][0], wa.x, p0); fma2(A[0][1], wa.y, p0);
            fma2(A[1][0], wa.x, p1); fma2(A[1][1], wa.y, p1);
            fma2(A[2][0], wa.x, p2); fma2(A[2][1], wa.y, p2);
            fma2(A[3][0], wa.x, p3); fma2(A[3][1], wa.y, p3);
            p0 = pk1(v0.y); p1 = pk1(v1.y); p2 = pk1(v2.y); p3 = pk1(v3.y);
            fma2(A[0][0], wb2.x, p0); fma2(A[0][1], wb2.y, p0);
            fma2(A[1][0], wb2.x, p1); fma2(A[1][1], wb2.y, p1);
            fma2(A[2][0], wb2.x, p2); fma2(A[2][1], wb2.y, p2);
            fma2(A[3][0], wb2.x, p3); fma2(A[3][1], wb2.y, p3);
            p0 = pk1(v0.z); p1 = pk1(v1.z); p2 = pk1(v2.z); p3 = pk1(v3.z);
            fma2(A[0][0], wc.x, p0); fma2(A[0][1], wc.y, p0);
            fma2(A[1][0], wc.x, p1); fma2(A[1][1], wc.y, p1);
            fma2(A[2][0], wc.x, p2); fma2(A[2][1], wc.y, p2);
            fma2(A[3][0], wc.x, p3); fma2(A[3][1], wc.y, p3);
            p0 = pk1(v0.w); p1 = pk1(v1.w); p2 = pk1(v2.w); p3 = pk1(v3.w);
            fma2(A[0][0], wd.x, p0); fma2(A[0][1], wd.y, p0);
            fma2(A[1][0], wd.x, p1); fma2(A[1][1], wd.y, p1);
            fma2(A[2][0], wd.x, p2); fma2(A[2][1], wd.y, p2);
            fma2(A[3][0], wd.x, p3); fma2(A[3][1], wd.y, p3);
        }
        const ulonglong2* hrp = (const ulonglong2*)hrs;
        const ulonglong2* hip = (const ulonglong2*)his;
#pragma unroll
        for (int kt = 0; kt < 16; kt++) {
            ulonglong2 HR = hrp[kt * 16 + og];
            ulonglong2 HI = hip[kt * 16 + og];
#pragma unroll
            for (int tt = 0; tt < 4; tt++) {
                float2 e = ett_s[(t0 + tt) * 16 + kt];
                u64 er2 = pk1(e.x), ei2 = pk1(e.y);
                fma2(A[tt][0], HR.x, er2); fma2(A[tt][0], HI.x, ei2);
                fma2(A[tt][1], HR.y, er2); fma2(A[tt][1], HI.y, ei2);
            }
        }
    }
    __syncthreads();
    if (t0 < 49) {
#pragma unroll
        for (int tt = 0; tt < 4; tt++) {
            int t = t0 + tt;
            if (t < 49) {
                float2 lo = up2(A[tt][0]), hi = up2(A[tt][1]);
                float4 f4;
                if (!last) {
                    f4 = make_float4(gelu_f(lo.x), gelu_f(lo.y), gelu_f(hi.x), gelu_f(hi.y));
                    ((float4*)v_sh)[t * 16 + og] = f4;
                } else {
                    f4 = make_float4(lo.x, lo.y, hi.x, hi.y);
                    ((float4*)(g_v + vb))[t * 16 + og] = f4;
                }
            }
        }
    }
    if (!last) {
        __syncthreads();
        // write v back to global (all threads)
        for (int i = tid; i < 784; i += 256)
            ((float4*)(g_v + vb))[i] = ((const float4*)v_sh)[i];
        // fwd t-DFT spread over all 256 threads: (cg, kt)
        int cg = tid & 15, kt = tid >> 4;
        const ulonglong2* vp2 = (const ulonglong2*)v_sh;
        u64 Ar0 = 0ull, Ar1 = 0ull, Ai0 = 0ull, Ai1 = 0ull;
#pragma unroll 7
        for (int t = 0; t < 49; t++) {
            ulonglong2 v2 = vp2[t * 16 + cg];
            float2 e = ett_s[t * 16 + kt];
            u64 er2 = pk1(e.x), ei2 = pk1(e.y);
            fma2(Ar0, v2.x, er2); fma2(Ar1, v2.y, er2);
            fma2(Ai0, v2.x, ei2); fma2(Ai1, v2.y, ei2);
        }
        size_t ab = ((size_t)(b * XD + x)) * 16;
        float2 r0 = up2(Ar0), r1 = up2(Ar1), i0 = up2(Ai0), i1 = up2(Ai1);
        ((float4*)(g_hr + (ab + kt) * 64))[cg] = make_float4(r0.x, r0.y, r1.x, r1.y);
        ((float4*)(g_hi + (ab + kt) * 64))[cg] = make_float4(i0.x, i0.y, i1.x, i1.y);
    }
}

// ---------- crop + fc1 + gelu + fc2 (f32x2) ----------
__global__ void __launch_bounds__(256) k_final(const float* __restrict__ w1,
                                               const float* __restrict__ b1,
                                               const float* __restrict__ w2,
                                               const float* __restrict__ b2,
                                               float* __restrict__ out) {
    __shared__ __align__(16) float w1s[64 * 128];
    __shared__ __align__(16) float vs[40 * 64];
    __shared__ __align__(16) float b1s[128], w2s[128];
    __shared__ float b2s;
    int x = blockIdx.x, b = blockIdx.y, tid = threadIdx.x;
    for (int i = tid; i < 8192; i += 256) w1s[i] = w1[i];
    if (tid < 128) { b1s[tid] = b1[tid]; w2s[tid] = w2[tid]; }
    if (tid == 0) b2s = b2[0];
    size_t vb = ((size_t)(b * XD + x)) * VROW;
    for (int i = tid; i < 640; i += 256) ((float4*)vs)[i] = ((const float4*)(g_v + vb))[i];
    __syncthreads();
    int lane = tid & 31, wp = tid >> 5;
    u64 H[5][2];
    ulonglong2 bq = ((const ulonglong2*)b1s)[lane];
#pragma unroll
    for (int s = 0; s < 5; s++) { H[s][0] = bq.x; H[s][1] = bq.y; }
    const ulonglong2* w1p = (const ulonglong2*)w1s;
#pragma unroll 4
    for (int c = 0; c < 64; c++) {
        ulonglong2 w2v = w1p[c * 32 + lane];
#pragma unroll
        for (int s = 0; s < 5; s++) {
            u64 vv = pk1(vs[(wp + 8 * s) * 64 + c]);
            fma2(H[s][0], w2v.x, vv);
            fma2(H[s][1], w2v.y, vv);
        }
    }
    float4 w2q = ((const float4*)w2s)[lane];
#pragma unroll
    for (int s = 0; s < 5; s++) {
        float2 hlo = up2(H[s][0]), hhi = up2(H[s][1]);
        float acc = gelu_f(hlo.x) * w2q.x + gelu_f(hlo.y) * w2q.y +
                    gelu_f(hhi.x) * w2q.z + gelu_f(hhi.y) * w2q.w;
#pragma unroll
        for (int off = 16; off; off >>= 1) acc += __shfl_xor_sync(0xffffffffu, acc, off);
        if (lane == 0) out[((size_t)(b * 512 + x)) * 40 + wp + 8 * s] = acc + b2s;
    }
}

extern "C" void kernel_launch(void* const* d_in, const int* in_sizes, int n_in,
                              void* d_out, int out_size) {
    (void)in_sizes; (void)n_in; (void)out_size;
    const float* u      = (const float*)d_in[0];
    const float* xin    = (const float*)d_in[1];
    const float* tin    = (const float*)d_in[2];
    const float* par    = (const float*)d_in[3];
    const float* fc0_w  = (const float*)d_in[4];
    const float* fc0_b  = (const float*)d_in[5];
    const float* spec_wr = (const float*)d_in[6];
    const float* spec_wi = (const float*)d_in[7];
    const float* w_conv = (const float*)d_in[8];
    const float* w_bias = (const float*)d_in[9];
    const float* fc1_w  = (const float*)d_in[10];
    const float* fc1_b  = (const float*)d_in[11];
    const float* fc2_w  = (const float*)d_in[12];
    const float* fc2_b  = (const float*)d_in[13];
    float* out = (float*)d_out;

    k_tables<<<33, 256>>>();
    k_wt<<<dim3(4, 64, 4), 256>>>(spec_wr, spec_wi);
    k_embed<<<dim3(131, NB), 256>>>(u, xin, tin, par, fc0_w, fc0_b);
    for (int l = 0; l < 4; l++) {
        k_dft_x<<<dim3(8, 2, NB), 256>>>();
        k_mix<<<dim3(256, 2), 256, 40960>>>(l);
        k_idft_x<<<dim3(66, NB), 256>>>();
        k_conv_inv<<<dim3(XD, NB), 256>>>(w_conv, w_bias, l, l == 3 ? 1 : 0);
    }
    k_final<<<dim3(512, NB), 256>>>(fc1_w, fc1_b, fc2_w, fc2_b, out);
}

// round 9
// speedup vs baseline: 1.2579x; 1.1746x over previous
#include <cuda_runtime.h>
#include <math.h>

#define NB 32
#define XD 521
#define TD 49
#define CW 64
#define VROW 3136                 // TD*CW
#define V_ELEMS  52283392ull      // NB*XD*VROW
#define PC_ELEMS 1605632ull      // NB*16*VROW (float2)
#define WT_ELEMS 4194304ull      // 4*256*64*64 (float2)

typedef unsigned long long u64;

__device__ float g_v[V_ELEMS];
__device__ float g_u1[V_ELEMS];
__device__ float2 g_pc[PC_ELEMS];     // P[b][kx][t*64+c]
__device__ float2 g_rc[PC_ELEMS];     // R[b][kx][t*64+o]
__device__ float2 g_wt1[WT_ELEMS];    // (wr, wi)  [l][m][c][o]
__device__ float2 g_wt2[WT_ELEMS];    // (-wi, wr)
__device__ float2 g_exE[16 * 521];    // (cos(-th), sin(-th))  fwd x twiddle
__device__ float2 g_et1[784];         // [kt][t] (er, ei)  fwd t
__device__ float2 g_et2[784];         // (-ei, er)
__device__ float2 g_ct1[784];         // [kt][t] (ct, cs)  inv t (scaled)
__device__ float2 g_ct2[784];         // (-cs, ct)

__device__ __forceinline__ float gelu_f(float v) {
    return 0.5f * v * (1.0f + erff(v * 0.70710678118654752f));
}
__device__ __forceinline__ u64 pk(float lo, float hi) {
    u64 r; asm("mov.b64 %0,{%1,%2};" : "=l"(r) : "f"(lo), "f"(hi)); return r;
}
__device__ __forceinline__ u64 pk1(float v) { return pk(v, v); }
__device__ __forceinline__ void fma2(u64& d, u64 a, u64 b) {
    asm("fma.rn.f32x2 %0,%1,%2,%0;" : "+l"(d) : "l"(a), "l"(b));
}
__device__ __forceinline__ void add2(u64& d, u64 a) {
    asm("add.rn.f32x2 %0,%0,%1;" : "+l"(d) : "l"(a));
}
__device__ __forceinline__ float2 up2(u64 v) {
    float2 r; asm("mov.b64 {%0,%1},%2;" : "=f"(r.x), "=f"(r.y) : "l"(v)); return r;
}

// ---------- tables ----------
__global__ void k_tables() {
    int idx = blockIdx.x * blockDim.x + threadIdx.x;
    const double PI2 = 6.283185307179586476925287;
    if (idx < 784) {
        int kt = idx / 49, t = idx % 49;
        double a = -PI2 * (double)((kt * t) % 49) / 49.0;
        float er = (float)cos(a), ei = (float)sin(a);
        g_et1[idx] = make_float2(er, ei);
        g_et2[idx] = make_float2(-ei, er);
        float w = (kt == 0 ? 1.0f : 2.0f) * (float)(1.0 / (521.0 * 49.0));
        float ct = w * er;        // cos(+w) = er
        float cs = w * (-ei);     // sin(+w) = -ei
        g_ct1[idx] = make_float2(ct, cs);
        g_ct2[idx] = make_float2(-cs, ct);
    }
    if (idx < 8336) {
        int kx = idx / 521, x = idx % 521;
        double a = -PI2 * (double)((kx * x) % 521) / 521.0;
        g_exE[idx] = make_float2((float)cos(a), (float)sin(a));
    }
}

// ---------- spectral weight pack: [l][i][o][m] -> [l][m][c][o] pairs ----------
__global__ void k_wt2(const float* __restrict__ wr, const float* __restrict__ wi) {
    __shared__ float shr[64 * 65], shi[64 * 65];
    int mc = blockIdx.x, i = blockIdx.y, l = blockIdx.z, tid = threadIdx.x;
    size_t srcbase = ((size_t)(l * 64 + i)) * 64 * 256 + (size_t)mc * 64;
    for (int idx = tid; idx < 4096; idx += 256) {
        int o = idx >> 6, mm = idx & 63;
        shr[o * 65 + mm] = wr[srcbase + (size_t)o * 256 + mm];
        shi[o * 65 + mm] = wi[srcbase + (size_t)o * 256 + mm];
    }
    __syncthreads();
    for (int idx = tid; idx < 4096; idx += 256) {
        int mm = idx >> 6, o = idx & 63;
        int m = mc * 64 + mm;
        float r = shr[o * 65 + mm], im = shi[o * 65 + mm];
        size_t d = (((size_t)(l * 256 + m)) * 64 + i) * 64 + o;
        g_wt1[d] = make_float2(r, im);
        g_wt2[d] = make_float2(-im, r);
    }
}

// ---------- embed: fc0 into padded v ----------
__global__ void __launch_bounds__(256) k_embed(const float* __restrict__ u,
                                               const float* __restrict__ xin,
                                               const float* __restrict__ tin,
                                               const float* __restrict__ par,
                                               const float* __restrict__ w0,
                                               const float* __restrict__ b0) {
    __shared__ float feat[4][16];
    __shared__ float tv[40];
    int xq = blockIdx.x, b = blockIdx.y, tid = threadIdx.x;
    int xh = tid >> 6, c = tid & 63;
    int x = xq * 4 + xh;
    if (tid < 40) tv[tid] = tin[b * 40 + tid];
    if (c < 13 && x < 512) {
        float f;
        if (c < 10) f = u[((size_t)(b * 512 + x)) * 10 + c];
        else if (c < 12) f = par[b * 2 + c - 10];
        else f = xin[b * 512 + x];
        feat[xh][c] = f;
    }
    __syncthreads();
    if (x >= XD) return;
    bool vx = (x < 512);
    size_t vb = ((size_t)(b * XD + x)) * VROW;
    float basev = 0.f, w13c = 0.f;
    if (vx) {
        basev = b0[c];
#pragma unroll
        for (int k = 0; k < 13; k++) basev += feat[xh][k] * w0[k * 64 + c];
        w13c = w0[13 * 64 + c];
    }
    for (int t = 0; t < 40; t++)
        g_v[vb + t * 64 + c] = vx ? fmaf(tv[t], w13c, basev) : 0.f;
    for (int t = 40; t < 49; t++) g_v[vb + t * 64 + c] = 0.f;
}

// ---------- forward x-DFT: v real -> P[b][kx][j] complex ----------
__global__ void __launch_bounds__(224) k_fx() {
    __shared__ float2 exs[16 * 132];
    int jt = blockIdx.x, b = blockIdx.y, tid = threadIdx.x;
    int col0 = (jt * 224 + tid) * 2;
    size_t vb = (size_t)b * XD * VROW;
    u64 a0[16], a1[16];
#pragma unroll
    for (int kx = 0; kx < 16; kx++) { a0[kx] = 0ull; a1[kx] = 0ull; }
    for (int ch = 0; ch < 4; ch++) {
        int x0 = ch * 131;
        int cnt = min(131, XD - x0);
        __syncthreads();
        for (int i = tid; i < 16 * cnt; i += 224) {
            int kx = i / cnt, xl = i - kx * cnt;
            exs[kx * 132 + xl] = g_exE[kx * 521 + x0 + xl];
        }
        __syncthreads();
        for (int xl = 0; xl < cnt; xl++) {
            u64 v2 = *(const u64*)(g_v + vb + (size_t)(x0 + xl) * VROW + col0);
            float2 vv = up2(v2);
            u64 va = pk1(vv.x), vc = pk1(vv.y);
#pragma unroll
            for (int kx = 0; kx < 16; kx++) {
                u64 E = *(const u64*)&exs[kx * 132 + xl];
                fma2(a0[kx], va, E);
                fma2(a1[kx], vc, E);
            }
        }
    }
#pragma unroll
    for (int kx = 0; kx < 16; kx++) {
        ulonglong2 st;
        st.x = a0[kx]; st.y = a1[kx];
        *(ulonglong2*)(&g_pc[((size_t)(b * 16 + kx)) * VROW + col0]) = st;
    }
}

// ---------- spectral: t-DFT + channel mix + inv t-DFT per (kx, b) ----------
__global__ void __launch_bounds__(256) k_spec(int l) {
    __shared__ float2 Ps[VROW];    // 25KB
    __shared__ float2 Qs[1024];    // 8KB
    __shared__ float2 Ss[1024];    // 8KB
    int kx = blockIdx.x, b = blockIdx.y, tid = threadIdx.x;
    size_t base = ((size_t)(b * 16 + kx)) * VROW;
    for (int i = tid; i < VROW; i += 256) Ps[i] = g_pc[base + i];
    __syncthreads();
    // t-DFT: Q[kt][c]
    for (int i = tid; i < 1024; i += 256) {
        int kt = i >> 6, c = i & 63;
        u64 Q = 0ull;
        for (int t = 0; t < 49; t++) {
            float2 P = Ps[t * 64 + c];
            u64 e1 = *(const u64*)&g_et1[kt * 49 + t];
            u64 e2 = *(const u64*)&g_et2[kt * 49 + t];
            fma2(Q, pk1(P.x), e1);
            fma2(Q, pk1(P.y), e2);
        }
        Qs[i] = up2(Q);
    }
    __syncthreads();
    // mix: S[kt][o]
    for (int i = tid; i < 1024; i += 256) {
        int kt = i >> 6, o = i & 63;
        u64 S = 0ull;
        size_t wb = ((size_t)(l * 256 + kx * 16 + kt)) * 4096 + o;
        for (int c = 0; c < 64; c++) {
            float2 q = Qs[kt * 64 + c];
            u64 w1 = *(const u64*)&g_wt1[wb + c * 64];
            u64 w2 = *(const u64*)&g_wt2[wb + c * 64];
            fma2(S, pk1(q.x), w1);
            fma2(S, pk1(q.y), w2);
        }
        Ss[i] = up2(S);
    }
    __syncthreads();
    // inv t-DFT: R[t][o] (scaled, a_kt folded)
    for (int i = tid; i < VROW; i += 256) {
        int t = i >> 6, o = i & 63;
        u64 R = 0ull;
#pragma unroll
        for (int kt = 0; kt < 16; kt++) {
            float2 s = Ss[kt * 64 + o];
            u64 c1 = *(const u64*)&g_ct1[kt * 49 + t];
            u64 c2 = *(const u64*)&g_ct2[kt * 49 + t];
            fma2(R, pk1(s.x), c1);
            fma2(R, pk1(s.y), c2);
        }
        g_rc[base + i] = up2(R);
    }
}

// ---------- inverse x-DFT: R -> u1 real ----------
__global__ void __launch_bounds__(224) k_ix() {
    __shared__ float2 exs[16 * 176];
    int jt = blockIdx.x, xc = blockIdx.y, b = blockIdx.z, tid = threadIdx.x;
    int col0 = (jt * 224 + tid) * 2;
    int x0 = xc * 174;
    int cnt = min(174, XD - x0);
    ulonglong2 Rv[16];
#pragma unroll
    for (int kx = 0; kx < 16; kx++)
        Rv[kx] = *(const ulonglong2*)(&g_rc[((size_t)(b * 16 + kx)) * VROW + col0]);
    for (int i = tid; i < 16 * cnt; i += 224) {
        int kx = i / cnt, xl = i - kx * cnt;
        exs[kx * 176 + xl] = g_exE[kx * 521 + x0 + xl];
    }
    __syncthreads();
    for (int xl = 0; xl < cnt; xl++) {
        u64 d0 = 0ull, d1 = 0ull;
#pragma unroll
        for (int kx = 0; kx < 16; kx++) {
            u64 E = *(const u64*)&exs[kx * 176 + xl];
            fma2(d0, Rv[kx].x, E);
            fma2(d1, Rv[kx].y, E);
        }
        float2 f0 = up2(d0), f1 = up2(d1);
        *(u64*)(g_u1 + (size_t)(b * XD + x0 + xl) * VROW + col0) = pk(f0.x + f0.y, f1.x + f1.y);
    }
}

// ---------- conv (64x64) + bias + u1 + gelu, in-place on v ----------
__global__ void __launch_bounds__(128) k_conv(const float* __restrict__ wconv,
                                              const float* __restrict__ wbias,
                                              int l, int last) {
    __shared__ __align__(16) float v_sh[3328];
    __shared__ __align__(16) float wT[4096];
    __shared__ __align__(16) float bsh[64];
    int x = blockIdx.x, b = blockIdx.y, tid = threadIdx.x;
    size_t vb = ((size_t)(b * XD + x)) * VROW;
    for (int i = tid; i < 784; i += 128) ((float4*)v_sh)[i] = ((const float4*)(g_v + vb))[i];
    for (int i = 3136 + tid; i < 3328; i += 128) v_sh[i] = 0.f;
    for (int i = tid; i < 4096; i += 128) {
        int o = i >> 6, c = i & 63;
        wT[c * 64 + o] = wconv[l * 4096 + i];
    }
    if (tid < 64) bsh[tid] = wbias[l * 64 + tid];
    __syncthreads();

    int og = tid & 7, tg = tid >> 3;
    int t0 = tg * 4;
    if (t0 >= 49) return;
    u64 A[4][4];
    {
        const ulonglong2* bp = (const ulonglong2*)bsh;
        ulonglong2 B0 = bp[og * 2], B1 = bp[og * 2 + 1];
#pragma unroll
        for (int tt = 0; tt < 4; tt++) {
            A[tt][0] = B0.x; A[tt][1] = B0.y; A[tt][2] = B1.x; A[tt][3] = B1.y;
        }
    }
    const float4* v4p = (const float4*)v_sh;
    const ulonglong2* wp2 = (const ulonglong2*)wT;
#pragma unroll 4
    for (int cq = 0; cq < 16; cq++) {
        float4 v0 = v4p[(t0 + 0) * 16 + cq];
        float4 v1 = v4p[(t0 + 1) * 16 + cq];
        float4 v2 = v4p[(t0 + 2) * 16 + cq];
        float4 v3 = v4p[(t0 + 3) * 16 + cq];
#pragma unroll
        for (int cc = 0; cc < 4; cc++) {
            int c = cq * 4 + cc;
            ulonglong2 W0 = wp2[c * 16 + og * 2];
            ulonglong2 W1 = wp2[c * 16 + og * 2 + 1];
            float s0 = (cc == 0) ? v0.x : (cc == 1) ? v0.y : (cc == 2) ? v0.z : v0.w;
            float s1 = (cc == 0) ? v1.x : (cc == 1) ? v1.y : (cc == 2) ? v1.z : v1.w;
            float s2 = (cc == 0) ? v2.x : (cc == 1) ? v2.y : (cc == 2) ? v2.z : v2.w;
            float s3 = (cc == 0) ? v3.x : (cc == 1) ? v3.y : (cc == 2) ? v3.z : v3.w;
            u64 p0 = pk1(s0), p1 = pk1(s1), p2 = pk1(s2), p3 = pk1(s3);
            fma2(A[0][0], W0.x, p0); fma2(A[0][1], W0.y, p0); fma2(A[0][2], W1.x, p0); fma2(A[0][3], W1.y, p0);
            fma2(A[1][0], W0.x, p1); fma2(A[1][1], W0.y, p1); fma2(A[1][2], W1.x, p1); fma2(A[1][3], W1.y, p1);
            fma2(A[2][0], W0.x, p2); fma2(A[2][1], W0.y, p2); fma2(A[2][2], W1.x, p2); fma2(A[2][3], W1.y, p2);
            fma2(A[3][0], W0.x, p3); fma2(A[3][1], W0.y, p3); fma2(A[3][2], W1.x, p3); fma2(A[3][3], W1.y, p3);
        }
    }
#pragma unroll
    for (int tt = 0; tt < 4; tt++) {
        int t = t0 + tt;
        if (t < 49) {
            size_t bu = vb + t * 64 + og * 8;
            ulonglong2 U0 = *(const ulonglong2*)(g_u1 + bu);
            ulonglong2 U1 = *(const ulonglong2*)(g_u1 + bu + 4);
            add2(A[tt][0], U0.x); add2(A[tt][1], U0.y);
            add2(A[tt][2], U1.x); add2(A[tt][3], U1.y);
            float2 r0 = up2(A[tt][0]), r1 = up2(A[tt][1]);
            float2 r2 = up2(A[tt][2]), r3 = up2(A[tt][3]);
            float4 fa, fb;
            if (!last) {
                fa = make_float4(gelu_f(r0.x), gelu_f(r0.y), gelu_f(r1.x), gelu_f(r1.y));
                fb = make_float4(gelu_f(r2.x), gelu_f(r2.y), gelu_f(r3.x), gelu_f(r3.y));
            } else {
                fa = make_float4(r0.x, r0.y, r1.x, r1.y);
                fb = make_float4(r2.x, r2.y, r3.x, r3.y);
            }
            ((float4*)(g_v + vb))[t * 16 + og * 2] = fa;
            ((float4*)(g_v + vb))[t * 16 + og * 2 + 1] = fb;
        }
    }
}

// ---------- crop + fc1 + gelu + fc2 ----------
__global__ void __launch_bounds__(256) k_final(const float* __restrict__ w1,
                                               const float* __restrict__ b1,
                                               const float* __restrict__ w2,
                                               const float* __restrict__ b2,
                                               float* __restrict__ out) {
    __shared__ __align__(16) float w1s[64 * 128];
    __shared__ __align__(16) float vs[40 * 64];
    __shared__ __align__(16) float b1s[128], w2s[128];
    __shared__ float b2s;
    int x = blockIdx.x, b = blockIdx.y, tid = threadIdx.x;
    for (int i = tid; i < 8192; i += 256) w1s[i] = w1[i];
    if (tid < 128) { b1s[tid] = b1[tid]; w2s[tid] = w2[tid]; }
    if (tid == 0) b2s = b2[0];
    size_t vb = ((size_t)(b * XD + x)) * VROW;
    for (int i = tid; i < 640; i += 256) ((float4*)vs)[i] = ((const float4*)(g_v + vb))[i];
    __syncthreads();
    int lane = tid & 31, wp = tid >> 5;
    u64 H[5][2];
    ulonglong2 bq = ((const ulonglong2*)b1s)[lane];
#pragma unroll
    for (int s = 0; s < 5; s++) { H[s][0] = bq.x; H[s][1] = bq.y; }
    const ulonglong2* w1p = (const ulonglong2*)w1s;
#pragma unroll 4
    for (int c = 0; c < 64; c++) {
        ulonglong2 w2v = w1p[c * 32 + lane];
#pragma unroll
        for (int s = 0; s < 5; s++) {
            u64 vv = pk1(vs[(wp + 8 * s) * 64 + c]);
            fma2(H[s][0], w2v.x, vv);
            fma2(H[s][1], w2v.y, vv);
        }
    }
    float4 w2q = ((const float4*)w2s)[lane];
#pragma unroll
    for (int s = 0; s < 5; s++) {
        float2 hlo = up2(H[s][0]), hhi = up2(H[s][1]);
        float acc = gelu_f(hlo.x) * w2q.x + gelu_f(hlo.y) * w2q.y +
                    gelu_f(hhi.x) * w2q.z + gelu_f(hhi.y) * w2q.w;
#pragma unroll
        for (int off = 16; off; off >>= 1) acc += __shfl_xor_sync(0xffffffffu, acc, off);
        if (lane == 0) out[((size_t)(b * 512 + x)) * 40 + wp + 8 * s] = acc + b2s;
    }
}

extern "C" void kernel_launch(void* const* d_in, const int* in_sizes, int n_in,
                              void* d_out, int out_size) {
    (void)in_sizes; (void)n_in; (void)out_size;
    const float* u      = (const float*)d_in[0];
    const float* xin    = (const float*)d_in[1];
    const float* tin    = (const float*)d_in[2];
    const float* par    = (const float*)d_in[3];
    const float* fc0_w  = (const float*)d_in[4];
    const float* fc0_b  = (const float*)d_in[5];
    const float* spec_wr = (const float*)d_in[6];
    const float* spec_wi = (const float*)d_in[7];
    const float* w_conv = (const float*)d_in[8];
    const float* w_bias = (const float*)d_in[9];
    const float* fc1_w  = (const float*)d_in[10];
    const float* fc1_b  = (const float*)d_in[11];
    const float* fc2_w  = (const float*)d_in[12];
    const float* fc2_b  = (const float*)d_in[13];
    float* out = (float*)d_out;

    k_tables<<<33, 256>>>();
    k_wt2<<<dim3(4, 64, 4), 256>>>(spec_wr, spec_wi);
    k_embed<<<dim3(131, NB), 256>>>(u, xin, tin, par, fc0_w, fc0_b);
    for (int l = 0; l < 4; l++) {
        k_fx<<<dim3(7, NB), 224>>>();
        k_spec<<<dim3(16, NB), 256>>>(l);
        k_ix<<<dim3(7, 3, NB), 224>>>();
        k_conv<<<dim3(XD, NB), 128>>>(w_conv, w_bias, l, l == 3 ? 1 : 0);
    }
    k_final<<<dim3(512, NB), 256>>>(fc1_w, fc1_b, fc2_w, fc2_b, out);
}

// round 10
// speedup vs baseline: 1.3589x; 1.0803x over previous
#include <cuda_runtime.h>
#include <math.h>

#define NB 32
#define XD 521
#define TD 49
#define CW 64
#define VROW 3136                 // TD*CW
#define V_ELEMS  52283392ull      // NB*XD*VROW
#define PC_ELEMS 1605632ull      // NB*16*VROW (float2)
#define WT_ELEMS 4194304ull      // 4*256*64*64 (float2)

typedef unsigned long long u64;

__device__ float g_v[V_ELEMS];
__device__ float g_u1[V_ELEMS];
__device__ float g_u1b[V_ELEMS];
__device__ float2 g_pc[PC_ELEMS];     // P partial (x-half 0)
__device__ float2 g_pc2[PC_ELEMS];    // P partial (x-half 1)
__device__ float2 g_rc[PC_ELEMS];     // R[b][kx][t*64+o]
__device__ float2 g_wt1[WT_ELEMS];    // (wr, wi)  [l][m][c][o]
__device__ float2 g_wt2[WT_ELEMS];    // (-wi, wr)
__device__ float2 g_exE[16 * 521];    // fwd x twiddle
__device__ float2 g_et1[784];         // [kt][t] fwd t
__device__ float2 g_et2[784];
__device__ float2 g_ct1[784];         // inv t (scaled)
__device__ float2 g_ct2[784];

__device__ __forceinline__ float gelu_f(float v) {
    return 0.5f * v * (1.0f + erff(v * 0.70710678118654752f));
}
__device__ __forceinline__ u64 pk(float lo, float hi) {
    u64 r; asm("mov.b64 %0,{%1,%2};" : "=l"(r) : "f"(lo), "f"(hi)); return r;
}
__device__ __forceinline__ u64 pk1(float v) { return pk(v, v); }
__device__ __forceinline__ void fma2(u64& d, u64 a, u64 b) {
    asm("fma.rn.f32x2 %0,%1,%2,%0;" : "+l"(d) : "l"(a), "l"(b));
}
__device__ __forceinline__ void add2(u64& d, u64 a) {
    asm("add.rn.f32x2 %0,%0,%1;" : "+l"(d) : "l"(a));
}
__device__ __forceinline__ float2 up2(u64 v) {
    float2 r; asm("mov.b64 {%0,%1},%2;" : "=f"(r.x), "=f"(r.y) : "l"(v)); return r;
}

// ---------- tables ----------
__global__ void k_tables() {
    int idx = blockIdx.x * blockDim.x + threadIdx.x;
    const double PI2 = 6.283185307179586476925287;
    if (idx < 784) {
        int kt = idx / 49, t = idx % 49;
        double a = -PI2 * (double)((kt * t) % 49) / 49.0;
        float er = (float)cos(a), ei = (float)sin(a);
        g_et1[idx] = make_float2(er, ei);
        g_et2[idx] = make_float2(-ei, er);
        float w = (kt == 0 ? 1.0f : 2.0f) * (float)(1.0 / (521.0 * 49.0));
        float ct = w * er;
        float cs = w * (-ei);
        g_ct1[idx] = make_float2(ct, cs);
        g_ct2[idx] = make_float2(-cs, ct);
    }
    if (idx < 8336) {
        int kx = idx / 521, x = idx % 521;
        double a = -PI2 * (double)((kx * x) % 521) / 521.0;
        g_exE[idx] = make_float2((float)cos(a), (float)sin(a));
    }
}

// ---------- spectral weight pack ----------
__global__ void k_wt2(const float* __restrict__ wr, const float* __restrict__ wi) {
    __shared__ float shr[64 * 65], shi[64 * 65];
    int mc = blockIdx.x, i = blockIdx.y, l = blockIdx.z, tid = threadIdx.x;
    size_t srcbase = ((size_t)(l * 64 + i)) * 64 * 256 + (size_t)mc * 64;
    for (int idx = tid; idx < 4096; idx += 256) {
        int o = idx >> 6, mm = idx & 63;
        shr[o * 65 + mm] = wr[srcbase + (size_t)o * 256 + mm];
        shi[o * 65 + mm] = wi[srcbase + (size_t)o * 256 + mm];
    }
    __syncthreads();
    for (int idx = tid; idx < 4096; idx += 256) {
        int mm = idx >> 6, o = idx & 63;
        int m = mc * 64 + mm;
        float r = shr[o * 65 + mm], im = shi[o * 65 + mm];
        size_t d = (((size_t)(l * 256 + m)) * 64 + i) * 64 + o;
        g_wt1[d] = make_float2(r, im);
        g_wt2[d] = make_float2(-im, r);
    }
}

// ---------- embed ----------
__global__ void __launch_bounds__(256) k_embed(const float* __restrict__ u,
                                               const float* __restrict__ xin,
                                               const float* __restrict__ tin,
                                               const float* __restrict__ par,
                                               const float* __restrict__ w0,
                                               const float* __restrict__ b0) {
    __shared__ float feat[4][16];
    __shared__ float tv[40];
    int xq = blockIdx.x, b = blockIdx.y, tid = threadIdx.x;
    int xh = tid >> 6, c = tid & 63;
    int x = xq * 4 + xh;
    if (tid < 40) tv[tid] = tin[b * 40 + tid];
    if (c < 13 && x < 512) {
        float f;
        if (c < 10) f = u[((size_t)(b * 512 + x)) * 10 + c];
        else if (c < 12) f = par[b * 2 + c - 10];
        else f = xin[b * 512 + x];
        feat[xh][c] = f;
    }
    __syncthreads();
    if (x >= XD) return;
    bool vx = (x < 512);
    size_t vb = ((size_t)(b * XD + x)) * VROW;
    float basev = 0.f, w13c = 0.f;
    if (vx) {
        basev = b0[c];
#pragma unroll
        for (int k = 0; k < 13; k++) basev += feat[xh][k] * w0[k * 64 + c];
        w13c = w0[13 * 64 + c];
    }
    for (int t = 0; t < 40; t++)
        g_v[vb + t * 64 + c] = vx ? fmaf(tv[t], w13c, basev) : 0.f;
    for (int t = 40; t < 49; t++) g_v[vb + t * 64 + c] = 0.f;
}

// ---------- forward x-DFT: kx-half x x-half split, partial accumulation ----------
__global__ void __launch_bounds__(224) k_fx() {
    __shared__ float2 exs[8 * 132];
    int jt = blockIdx.x;            // 0..6 col tile
    int q = blockIdx.y;             // 0..3 : kxh = q&1, xhf = q>>1
    int b = blockIdx.z;
    int tid = threadIdx.x;
    int kxh = (q & 1) * 8, xhf = q >> 1;
    int col0 = (jt * 224 + tid) * 2;
    int xbeg = xhf * 261, xend = xhf ? 521 : 261;
    size_t vb = (size_t)b * XD * VROW;
    u64 a0[8], a1[8];
#pragma unroll
    for (int kx = 0; kx < 8; kx++) { a0[kx] = 0ull; a1[kx] = 0ull; }
    for (int ch = 0; ch < 2; ch++) {
        int x0 = xbeg + ch * 131;
        int cnt = min(131, xend - x0);
        __syncthreads();
        for (int i = tid; i < 8 * cnt; i += 224) {
            int kx = i / cnt, xl = i - kx * cnt;
            exs[kx * 132 + xl] = g_exE[(kxh + kx) * 521 + x0 + xl];
        }
        __syncthreads();
        for (int xl = 0; xl < cnt; xl++) {
            u64 v2 = *(const u64*)(g_v + vb + (size_t)(x0 + xl) * VROW + col0);
            float2 vv = up2(v2);
            u64 va = pk1(vv.x), vc = pk1(vv.y);
#pragma unroll
            for (int kx = 0; kx < 8; kx++) {
                u64 E = *(const u64*)&exs[kx * 132 + xl];
                fma2(a0[kx], va, E);
                fma2(a1[kx], vc, E);
            }
        }
    }
    float2* dst = xhf ? g_pc2 : g_pc;
#pragma unroll
    for (int kx = 0; kx < 8; kx++) {
        ulonglong2 st;
        st.x = a0[kx]; st.y = a1[kx];
        *(ulonglong2*)(&dst[((size_t)(b * 16 + kxh + kx)) * VROW + col0]) = st;
    }
}

// ---------- spectral: t-DFT + channel mix + inv t-DFT per (kx, b) ----------
__global__ void __launch_bounds__(256) k_spec(int l) {
    __shared__ float2 Ps[VROW];    // 25KB
    __shared__ float2 Qs[1024];
    __shared__ float2 Ss[1024];
    int kx = blockIdx.x, b = blockIdx.y, tid = threadIdx.x;
    size_t base = ((size_t)(b * 16 + kx)) * VROW;
    for (int i = tid; i < VROW; i += 256) {
        float2 p0 = g_pc[base + i], p1 = g_pc2[base + i];
        Ps[i] = make_float2(p0.x + p1.x, p0.y + p1.y);
    }
    __syncthreads();
    // t-DFT: Q[kt][c]
    for (int i = tid; i < 1024; i += 256) {
        int kt = i >> 6, c = i & 63;
        u64 Q = 0ull;
        for (int t = 0; t < 49; t++) {
            float2 P = Ps[t * 64 + c];
            u64 e1 = *(const u64*)&g_et1[kt * 49 + t];
            u64 e2 = *(const u64*)&g_et2[kt * 49 + t];
            fma2(Q, pk1(P.x), e1);
            fma2(Q, pk1(P.y), e2);
        }
        Qs[i] = up2(Q);
    }
    __syncthreads();
    // mix: S[kt][o]
    for (int i = tid; i < 1024; i += 256) {
        int kt = i >> 6, o = i & 63;
        u64 S = 0ull;
        size_t wb = ((size_t)(l * 256 + kx * 16 + kt)) * 4096 + o;
        for (int c = 0; c < 64; c++) {
            float2 q = Qs[kt * 64 + c];
            u64 w1 = *(const u64*)&g_wt1[wb + c * 64];
            u64 w2 = *(const u64*)&g_wt2[wb + c * 64];
            fma2(S, pk1(q.x), w1);
            fma2(S, pk1(q.y), w2);
        }
        Ss[i] = up2(S);
    }
    __syncthreads();
    // inv t-DFT: R[t][o]
    for (int i = tid; i < VROW; i += 256) {
        int t = i >> 6, o = i & 63;
        u64 R = 0ull;
#pragma unroll
        for (int kt = 0; kt < 16; kt++) {
            float2 s = Ss[kt * 64 + o];
            u64 c1 = *(const u64*)&g_ct1[kt * 49 + t];
            u64 c2 = *(const u64*)&g_ct2[kt * 49 + t];
            fma2(R, pk1(s.x), c1);
            fma2(R, pk1(s.y), c2);
        }
        g_rc[base + i] = up2(R);
    }
}

// ---------- inverse x-DFT: kx-half split, partial real outputs ----------
__global__ void __launch_bounds__(224) k_ix() {
    __shared__ float2 exs[8 * 176];
    int jt = blockIdx.x;            // 0..6
    int yz = blockIdx.y;            // 0..5 : xc = yz>>1, kxh = (yz&1)*8
    int b = blockIdx.z;
    int tid = threadIdx.x;
    int xc = yz >> 1, kxh = (yz & 1) * 8;
    int col0 = (jt * 224 + tid) * 2;
    int x0 = xc * 174;
    int cnt = min(174, XD - x0);
    ulonglong2 Rv[8];
#pragma unroll
    for (int kx = 0; kx < 8; kx++)
        Rv[kx] = *(const ulonglong2*)(&g_rc[((size_t)(b * 16 + kxh + kx)) * VROW + col0]);
    for (int i = tid; i < 8 * cnt; i += 224) {
        int kx = i / cnt, xl = i - kx * cnt;
        exs[kx * 176 + xl] = g_exE[(kxh + kx) * 521 + x0 + xl];
    }
    __syncthreads();
    float* dst = kxh ? g_u1b : g_u1;
    for (int xl = 0; xl < cnt; xl++) {
        u64 d0 = 0ull, d1 = 0ull;
#pragma unroll
        for (int kx = 0; kx < 8; kx++) {
            u64 E = *(const u64*)&exs[kx * 176 + xl];
            fma2(d0, Rv[kx].x, E);
            fma2(d1, Rv[kx].y, E);
        }
        float2 f0 = up2(d0), f1 = up2(d1);
        *(u64*)(dst + (size_t)(b * XD + x0 + xl) * VROW + col0) = pk(f0.x + f0.y, f1.x + f1.y);
    }
}

// ---------- conv (64x64) + bias + u1a+u1b + gelu, in-place ----------
__global__ void __launch_bounds__(128) k_conv(const float* __restrict__ wconv,
                                              const float* __restrict__ wbias,
                                              int l, int last) {
    __shared__ __align__(16) float v_sh[3328];
    __shared__ __align__(16) float wT[4096];
    __shared__ __align__(16) float bsh[64];
    int x = blockIdx.x, b = blockIdx.y, tid = threadIdx.x;
    size_t vb = ((size_t)(b * XD + x)) * VROW;
    for (int i = tid; i < 784; i += 128) ((float4*)v_sh)[i] = ((const float4*)(g_v + vb))[i];
    for (int i = 3136 + tid; i < 3328; i += 128) v_sh[i] = 0.f;
    for (int i = tid; i < 4096; i += 128) {
        int o = i >> 6, c = i & 63;
        wT[c * 64 + o] = wconv[l * 4096 + i];
    }
    if (tid < 64) bsh[tid] = wbias[l * 64 + tid];
    __syncthreads();

    int og = tid & 7, tg = tid >> 3;
    int t0 = tg * 4;
    if (t0 >= 49) return;
    u64 A[4][4];
    {
        const ulonglong2* bp = (const ulonglong2*)bsh;
        ulonglong2 B0 = bp[og * 2], B1 = bp[og * 2 + 1];
#pragma unroll
        for (int tt = 0; tt < 4; tt++) {
            A[tt][0] = B0.x; A[tt][1] = B0.y; A[tt][2] = B1.x; A[tt][3] = B1.y;
        }
    }
    const float4* v4p = (const float4*)v_sh;
    const ulonglong2* wp2 = (const ulonglong2*)wT;
#pragma unroll 4
    for (int cq = 0; cq < 16; cq++) {
        float4 v0 = v4p[(t0 + 0) * 16 + cq];
        float4 v1 = v4p[(t0 + 1) * 16 + cq];
        float4 v2 = v4p[(t0 + 2) * 16 + cq];
        float4 v3 = v4p[(t0 + 3) * 16 + cq];
#pragma unroll
        for (int cc = 0; cc < 4; cc++) {
            int c = cq * 4 + cc;
            ulonglong2 W0 = wp2[c * 16 + og * 2];
            ulonglong2 W1 = wp2[c * 16 + og * 2 + 1];
            float s0 = (cc == 0) ? v0.x : (cc == 1) ? v0.y : (cc == 2) ? v0.z : v0.w;
            float s1 = (cc == 0) ? v1.x : (cc == 1) ? v1.y : (cc == 2) ? v1.z : v1.w;
            float s2 = (cc == 0) ? v2.x : (cc == 1) ? v2.y : (cc == 2) ? v2.z : v2.w;
            float s3 = (cc == 0) ? v3.x : (cc == 1) ? v3.y : (cc == 2) ? v3.z : v3.w;
            u64 p0 = pk1(s0), p1 = pk1(s1), p2 = pk1(s2), p3 = pk1(s3);
            fma2(A[0][0], W0.x, p0); fma2(A[0][1], W0.y, p0); fma2(A[0][2], W1.x, p0); fma2(A[0][3], W1.y, p0);
            fma2(A[1][0], W0.x, p1); fma2(A[1][1], W0.y, p1); fma2(A[1][2], W1.x, p1); fma2(A[1][3], W1.y, p1);
            fma2(A[2][0], W0.x, p2); fma2(A[2][1], W0.y, p2); fma2(A[2][2], W1.x, p2); fma2(A[2][3], W1.y, p2);
            fma2(A[3][0], W0.x, p3); fma2(A[3][1], W0.y, p3); fma2(A[3][2], W1.x, p3); fma2(A[3][3], W1.y, p3);
        }
    }
#pragma unroll
    for (int tt = 0; tt < 4; tt++) {
        int t = t0 + tt;
        if (t < 49) {
            size_t bu = vb + t * 64 + og * 8;
            ulonglong2 U0 = *(const ulonglong2*)(g_u1 + bu);
            ulonglong2 U1 = *(const ulonglong2*)(g_u1 + bu + 4);
            ulonglong2 V0 = *(const ulonglong2*)(g_u1b + bu);
            ulonglong2 V1 = *(const ulonglong2*)(g_u1b + bu + 4);
            add2(A[tt][0], U0.x); add2(A[tt][1], U0.y);
            add2(A[tt][2], U1.x); add2(A[tt][3], U1.y);
            add2(A[tt][0], V0.x); add2(A[tt][1], V0.y);
            add2(A[tt][2], V1.x); add2(A[tt][3], V1.y);
            float2 r0 = up2(A[tt][0]), r1 = up2(A[tt][1]);
            float2 r2 = up2(A[tt][2]), r3 = up2(A[tt][3]);
            float4 fa, fb;
            if (!last) {
                fa = make_float4(gelu_f(r0.x), gelu_f(r0.y), gelu_f(r1.x), gelu_f(r1.y));
                fb = make_float4(gelu_f(r2.x), gelu_f(r2.y), gelu_f(r3.x), gelu_f(r3.y));
            } else {
                fa = make_float4(r0.x, r0.y, r1.x, r1.y);
                fb = make_float4(r2.x, r2.y, r3.x, r3.y);
            }
            ((float4*)(g_v + vb))[t * 16 + og * 2] = fa;
            ((float4*)(g_v + vb))[t * 16 + og * 2 + 1] = fb;
        }
    }
}

// ---------- crop + fc1 + gelu + fc2 ----------
__global__ void __launch_bounds__(256) k_final(const float* __restrict__ w1,
                                               const float* __restrict__ b1,
                                               const float* __restrict__ w2,
                                               const float* __restrict__ b2,
                                               float* __restrict__ out) {
    __shared__ __align__(16) float w1s[64 * 128];
    __shared__ __align__(16) float vs[40 * 64];
    __shared__ __align__(16) float b1s[128], w2s[128];
    __shared__ float b2s;
    int x = blockIdx.x, b = blockIdx.y, tid = threadIdx.x;
    for (int i = tid; i < 8192; i += 256) w1s[i] = w1[i];
    if (tid < 128) { b1s[tid] = b1[tid]; w2s[tid] = w2[tid]; }
    if (tid == 0) b2s = b2[0];
    size_t vb = ((size_t)(b * XD + x)) * VROW;
    for (int i = tid; i < 640; i += 256) ((float4*)vs)[i] = ((const float4*)(g_v + vb))[i];
    __syncthreads();
    int lane = tid & 31, wp = tid >> 5;
    u64 H[5][2];
    ulonglong2 bq = ((const ulonglong2*)b1s)[lane];
#pragma unroll
    for (int s = 0; s < 5; s++) { H[s][0] = bq.x; H[s][1] = bq.y; }
    const ulonglong2* w1p = (const ulonglong2*)w1s;
#pragma unroll 4
    for (int c = 0; c < 64; c++) {
        ulonglong2 w2v = w1p[c * 32 + lane];
#pragma unroll
        for (int s = 0; s < 5; s++) {
            u64 vv = pk1(vs[(wp + 8 * s) * 64 + c]);
            fma2(H[s][0], w2v.x, vv);
            fma2(H[s][1], w2v.y, vv);
        }
    }
    float4 w2q = ((const float4*)w2s)[lane];
#pragma unroll
    for (int s = 0; s < 5; s++) {
        float2 hlo = up2(H[s][0]), hhi = up2(H[s][1]);
        float acc = gelu_f(hlo.x) * w2q.x + gelu_f(hlo.y) * w2q.y +
                    gelu_f(hhi.x) * w2q.z + gelu_f(hhi.y) * w2q.w;
#pragma unroll
        for (int off = 16; off; off >>= 1) acc += __shfl_xor_sync(0xffffffffu, acc, off);
        if (lane == 0) out[((size_t)(b * 512 + x)) * 40 + wp + 8 * s] = acc + b2s;
    }
}

extern "C" void kernel_launch(void* const* d_in, const int* in_sizes, int n_in,
                              void* d_out, int out_size) {
    (void)in_sizes; (void)n_in; (void)out_size;
    const float* u      = (const float*)d_in[0];
    const float* xin    = (const float*)d_in[1];
    const float* tin    = (const float*)d_in[2];
    const float* par    = (const float*)d_in[3];
    const float* fc0_w  = (const float*)d_in[4];
    const float* fc0_b  = (const float*)d_in[5];
    const float* spec_wr = (const float*)d_in[6];
    const float* spec_wi = (const float*)d_in[7];
    const float* w_conv = (const float*)d_in[8];
    const float* w_bias = (const float*)d_in[9];
    const float* fc1_w  = (const float*)d_in[10];
    const float* fc1_b  = (const float*)d_in[11];
    const float* fc2_w  = (const float*)d_in[12];
    const float* fc2_b  = (const float*)d_in[13];
    float* out = (float*)d_out;

    k_tables<<<33, 256>>>();
    k_wt2<<<dim3(4, 64, 4), 256>>>(spec_wr, spec_wi);
    k_embed<<<dim3(131, NB), 256>>>(u, xin, tin, par, fc0_w, fc0_b);
    for (int l = 0; l < 4; l++) {
        k_fx<<<dim3(7, 4, NB), 224>>>();
        k_spec<<<dim3(16, NB), 256>>>(l);
        k_ix<<<dim3(7, 6, NB), 224>>>();
        k_conv<<<dim3(XD, NB), 128>>>(w_conv, w_bias, l, l == 3 ? 1 : 0);
    }
    k_final<<<dim3(512, NB), 256>>>(fc1_w, fc1_b, fc2_w, fc2_b, out);
}